// round 14
// baseline (speedup 1.0000x reference)
#include <cuda_runtime.h>
#include <cuda_bf16.h>
#include <math.h>

// ---------------- problem constants ----------------
#define HH 512
#define WW 512
#define CC 96
#define HWSZ (HH * WW)            // 262144
#define WIN 8
#define SHIFT 4
#define NTOK 64
#define NWIN 4096
#define HEADS 6
#define HD 16
#define MLPH 384
#define EPS 1e-5f

typedef unsigned int u32;

__device__ __forceinline__ float4 ld4s(const float* p) {
    return *reinterpret_cast<const float4*>(p);
}

// ---------------- scratch ----------------
__device__ float g_xw[NWIN * NTOK * CC];   // LN1'd, shifted, windowed tokens [win][tok][96]
__device__ float g_y[NWIN * NTOK * CC];    // attention+proj output [win][tok][96]
__device__ float g_x1T[CC * HWSZ];         // residual-1, TRANSPOSED [c][p]
__device__ float g_hnT[CC * HWSZ];         // LN2 output,  TRANSPOSED [c][p]

// ---------------- precomputed bf16 hi/lo weight splits (u32 = 2 bf16, k-pairs) ----
__device__ u32 g_qh[288 * 48],  g_ql[288 * 48];    // qkv_w
__device__ u32 g_ph[96 * 48],   g_pl[96 * 48];     // proj_w
__device__ u32 g_w1h[384 * 48], g_w1l[384 * 48];   // fc1_w
__device__ u32 g_w2h[96 * 192], g_w2l[96 * 192];   // fc2_w

// ---------------- bf16 split helpers ----------------
__device__ __forceinline__ void bf16_split(float v, unsigned short& h, unsigned short& l) {
    __nv_bfloat16 hb = __float2bfloat16(v);
    __nv_bfloat16 lb = __float2bfloat16(v - __bfloat162float(hb));
    h = __bfloat16_as_ushort(hb);
    l = __bfloat16_as_ushort(lb);
}
__device__ __forceinline__ u32 pack2(unsigned short a, unsigned short b) {
    return (u32)a | ((u32)b << 16);
}

// mma.sync m16n8k16 bf16 (baseline sm_80+ instruction; valid for sm_103 target)
__device__ __forceinline__ void mma_bf16(float* c, u32 a0, u32 a1, u32 a2, u32 a3,
                                         u32 b0, u32 b1) {
    asm volatile(
        "mma.sync.aligned.m16n8k16.row.col.f32.bf16.bf16.f32 "
        "{%0,%1,%2,%3}, {%4,%5,%6,%7}, {%8,%9}, {%0,%1,%2,%3};"
        : "+f"(c[0]), "+f"(c[1]), "+f"(c[2]), "+f"(c[3])
        : "r"(a0), "r"(a1), "r"(a2), "r"(a3), "r"(b0), "r"(b1));
}

// ============================================================================
// Kernel W: one-time split of all weight matrices into bf16 hi/lo u32 pairs.
// All matrices are row-major [n][k] with even k, so pair i covers elements 2i, 2i+1.
// ============================================================================
__global__ void k_split_w(const float* __restrict__ qkv_w, const float* __restrict__ proj_w,
                          const float* __restrict__ fc1_w, const float* __restrict__ fc2_w) {
    const int i = blockIdx.x * 256 + threadIdx.x;
    unsigned short h0, l0, h1, l1;
    if (i < 13824) {                      // qkv: 288*48
        bf16_split(qkv_w[2 * i], h0, l0);
        bf16_split(qkv_w[2 * i + 1], h1, l1);
        g_qh[i] = pack2(h0, h1); g_ql[i] = pack2(l0, l1);
    } else if (i < 18432) {               // proj: 96*48
        const int j = i - 13824;
        bf16_split(proj_w[2 * j], h0, l0);
        bf16_split(proj_w[2 * j + 1], h1, l1);
        g_ph[j] = pack2(h0, h1); g_pl[j] = pack2(l0, l1);
    } else if (i < 36864) {               // fc1: 384*48
        const int j = i - 18432;
        bf16_split(fc1_w[2 * j], h0, l0);
        bf16_split(fc1_w[2 * j + 1], h1, l1);
        g_w1h[j] = pack2(h0, h1); g_w1l[j] = pack2(l0, l1);
    } else if (i < 55296) {               // fc2: 96*192
        const int j = i - 36864;
        bf16_split(fc2_w[2 * j], h0, l0);
        bf16_split(fc2_w[2 * j + 1], h1, l1);
        g_w2h[j] = pack2(h0, h1); g_w2l[j] = pack2(l0, l1);
    }
}

// ============================================================================
// Kernel A: NCHW read + LayerNorm1 + cyclic shift + window partition
// ============================================================================
__global__ void k_ln1_window(const float* __restrict__ x,
                             const float* __restrict__ n1w,
                             const float* __restrict__ n1b) {
    __shared__ float s[CC * 65];
    const int h = blockIdx.y;
    const int w0 = blockIdx.x * 64;
    const int t = threadIdx.x;

    #pragma unroll 4
    for (int c = 0; c < CC; ++c)
        s[c * 65 + t] = x[c * HWSZ + h * WW + w0 + t];
    __syncthreads();

    float mu = 0.f;
    #pragma unroll 8
    for (int c = 0; c < CC; ++c) mu += s[c * 65 + t];
    mu *= (1.0f / CC);
    float var = 0.f;
    #pragma unroll 8
    for (int c = 0; c < CC; ++c) { float d = s[c * 65 + t] - mu; var += d * d; }
    var *= (1.0f / CC);
    const float rstd = rsqrtf(var + EPS);
    #pragma unroll 8
    for (int c = 0; c < CC; ++c)
        s[c * 65 + t] = (s[c * 65 + t] - mu) * rstd * n1w[c] + n1b[c];
    __syncthreads();

    for (int idx = t; idx < 64 * CC; idx += 64) {
        const int tt = idx / CC, c = idx - tt * CC;
        const int wp = w0 + tt;
        const int hs = (h - SHIFT) & (HH - 1);
        const int ws = (wp - SHIFT) & (WW - 1);
        const int win = (hs >> 3) * 64 + (ws >> 3);
        const int tok = ((hs & 7) << 3) + (ws & 7);
        g_xw[(win * NTOK + tok) * CC + c] = s[c * 65 + tt];
    }
}

// ============================================================================
// Kernel C: per-window attention. qkv + proj on tensor cores (bf16 split mma),
// S/softmax/PV scalar fp32.
// smem (bytes): [0,13312) X/PO hi (64x104 bf16) | [13312,26624) lo
//               [26624,101376) qk fp32 [64][292] | [101376,205824) sa [6][64][68]
// ============================================================================
#define AT_XH 0
#define AT_XL 13312
#define SMEM_ATTN 205824

__global__ __launch_bounds__(256, 1)
void k_attn(const float* __restrict__ qkv_b,
            const float* __restrict__ rpb,
            const float* __restrict__ proj_b) {
    extern __shared__ char smc[];
    float* qk = (float*)(smc + 26624);    // [64][292]: q 0..95, k 96..191, v 192..287
    float* sa = (float*)(smc + 101376);   // [6][64][68]
    __shared__ int rg[64];

    const int win = blockIdx.x;
    const int tid = threadIdx.x;
    const int wid = tid >> 5;
    const int lane = tid & 31;
    const int lg = lane >> 2;      // 0..7
    const int tg = lane & 3;       // 0..3
    const int wi = win >> 6, wj = win & 63;

    // ---- stage X: split LN1'd window tokens to bf16 hi/lo ----
    const float* src = g_xw + win * (NTOK * CC);
    for (int i = tid; i < 64 * 48; i += 256) {
        const int tok = i / 48, k2 = i - tok * 48;
        unsigned short h0, l0, h1, l1;
        bf16_split(src[tok * 96 + 2 * k2], h0, l0);
        bf16_split(src[tok * 96 + 2 * k2 + 1], h1, l1);
        const int off = (tok * 104 + 2 * k2) * 2;
        *(u32*)(smc + AT_XH + off) = pack2(h0, h1);
        *(u32*)(smc + AT_XL + off) = pack2(l0, l1);
    }
    if (tid < 64) {
        const int r1 = tid >> 3, c1 = tid & 7;
        const int a = (wi == 63) ? (r1 < SHIFT ? 1 : 2) : 0;
        const int b = (wj == 63) ? (c1 < SHIFT ? 1 : 2) : 0;
        rg[tid] = a * 3 + b;
    }
    __syncthreads();

    // ---- qkv GEMM via mma: C[64][288]. warp = (m-tile wid&3, n-half wid>>2) ----
    {
        const int m0 = (wid & 3) * 16;
        const int nb = (wid >> 2) * 144;
        float acc[18][4];
        #pragma unroll
        for (int nt = 0; nt < 18; ++nt)
            #pragma unroll
            for (int q = 0; q < 4; ++q) acc[nt][q] = 0.f;
        #pragma unroll
        for (int ks = 0; ks < 6; ++ks) {
            const int ra = (m0 + lg) * 104 + ks * 16 + tg * 2;
            const u32 ah0 = *(u32*)(smc + AT_XH + ra * 2);
            const u32 ah1 = *(u32*)(smc + AT_XH + (ra + 8 * 104) * 2);
            const u32 ah2 = *(u32*)(smc + AT_XH + (ra + 8) * 2);
            const u32 ah3 = *(u32*)(smc + AT_XH + (ra + 8 * 104 + 8) * 2);
            const u32 al0 = *(u32*)(smc + AT_XL + ra * 2);
            const u32 al1 = *(u32*)(smc + AT_XL + (ra + 8 * 104) * 2);
            const u32 al2 = *(u32*)(smc + AT_XL + (ra + 8) * 2);
            const u32 al3 = *(u32*)(smc + AT_XL + (ra + 8 * 104 + 8) * 2);
            #pragma unroll
            for (int nt = 0; nt < 18; ++nt) {
                const int bi = (nb + nt * 8 + lg) * 48 + ks * 8 + tg;
                const u32 bh0 = g_qh[bi], bh1 = g_qh[bi + 4];
                const u32 bl0 = g_ql[bi], bl1 = g_ql[bi + 4];
                mma_bf16(acc[nt], ah0, ah1, ah2, ah3, bh0, bh1);
                mma_bf16(acc[nt], ah0, ah1, ah2, ah3, bl0, bl1);
                mma_bf16(acc[nt], al0, al1, al2, al3, bh0, bh1);
            }
        }
        #pragma unroll
        for (int nt = 0; nt < 18; ++nt) {
            const int n0 = nb + nt * 8 + tg * 2;
            const float b0v = qkv_b[n0], b1v = qkv_b[n0 + 1];
            *(float2*)&qk[(m0 + lg) * 292 + n0] =
                make_float2(acc[nt][0] + b0v, acc[nt][1] + b1v);
            *(float2*)&qk[(m0 + lg + 8) * 292 + n0] =
                make_float2(acc[nt][2] + b0v, acc[nt][3] + b1v);
        }
    }
    __syncthreads();

    // ---- S = q k^T * scale + bias + mask (scalar, all heads) ----
    for (int gg = tid; gg < 768; gg += 256) {
        const int h = gg >> 7;
        const int rem = gg & 127;
        const int n0 = rem & 15;
        const int m0 = (rem >> 4) << 3;
        const int qo = h * 16, ko = 96 + h * 16;
        float qv[4][16];
        #pragma unroll
        for (int i = 0; i < 4; ++i) {
            #pragma unroll
            for (int k = 0; k < 4; ++k) {
                const float4 v = ld4s(&qk[(n0 + 16 * i) * 292 + qo + 4 * k]);
                qv[i][4 * k] = v.x; qv[i][4 * k + 1] = v.y;
                qv[i][4 * k + 2] = v.z; qv[i][4 * k + 3] = v.w;
            }
        }
        float acc[4][8];
        #pragma unroll
        for (int i = 0; i < 4; ++i)
            #pragma unroll
            for (int j = 0; j < 8; ++j) acc[i][j] = 0.f;
        #pragma unroll
        for (int j = 0; j < 8; ++j) {
            float kv[16];
            #pragma unroll
            for (int k = 0; k < 4; ++k) {
                const float4 v = ld4s(&qk[(m0 + j) * 292 + ko + 4 * k]);
                kv[4 * k] = v.x; kv[4 * k + 1] = v.y;
                kv[4 * k + 2] = v.z; kv[4 * k + 3] = v.w;
            }
            #pragma unroll
            for (int i = 0; i < 4; ++i) {
                float a = 0.f;
                #pragma unroll
                for (int d = 0; d < 16; ++d) a += qv[i][d] * kv[d];
                acc[i][j] = a;
            }
        }
        #pragma unroll
        for (int i = 0; i < 4; ++i) {
            const int n = n0 + 16 * i;
            const int r1 = n >> 3, c1 = n & 7;
            const int rgn = rg[n];
            float vo[8];
            #pragma unroll
            for (int j = 0; j < 8; ++j) {
                const int m = m0 + j;
                const int r2 = m >> 3, c2 = m & 7;
                float s = acc[i][j] * 0.25f
                        + rpb[((r1 - r2 + 7) * 15 + (c1 - c2 + 7)) * HEADS + h];
                if (rgn != rg[m]) s -= 100.0f;
                vo[j] = s;
            }
            *reinterpret_cast<float4*>(&sa[(h * 64 + n) * 68 + m0]) =
                make_float4(vo[0], vo[1], vo[2], vo[3]);
            *reinterpret_cast<float4*>(&sa[(h * 64 + n) * 68 + m0 + 4]) =
                make_float4(vo[4], vo[5], vo[6], vo[7]);
        }
    }
    __syncthreads();

    // ---- softmax: 384 rows ----
    for (int r = tid; r < 384; r += 256) {
        float* row = sa + r * 68;
        float mx = -1e30f;
        #pragma unroll
        for (int m = 0; m < 64; m += 4) {
            float4 v = *reinterpret_cast<float4*>(&row[m]);
            mx = fmaxf(mx, fmaxf(fmaxf(v.x, v.y), fmaxf(v.z, v.w)));
        }
        float sum = 0.f;
        #pragma unroll
        for (int m = 0; m < 64; m += 4) {
            float4 v = *reinterpret_cast<float4*>(&row[m]);
            v.x = __expf(v.x - mx); v.y = __expf(v.y - mx);
            v.z = __expf(v.z - mx); v.w = __expf(v.w - mx);
            sum += v.x + v.y + v.z + v.w;
            *reinterpret_cast<float4*>(&row[m]) = v;
        }
        const float inv = 1.0f / sum;
        #pragma unroll
        for (int m = 0; m < 64; m += 4) {
            float4 v = *reinterpret_cast<float4*>(&row[m]);
            v.x *= inv; v.y *= inv; v.z *= inv; v.w *= inv;
            *reinterpret_cast<float4*>(&row[m]) = v;
        }
    }
    __syncthreads();

    // ---- PV (scalar) -> write output pre-split bf16 hi/lo into X region ----
    if (tid < 192) {
        const int h = tid / 32;
        const int rem = tid & 31;
        const int n0 = rem & 15;
        const int d0 = (rem >> 4) << 3;
        const int vofs = 192 + h * 16 + d0;
        float acc[4][8];
        #pragma unroll
        for (int i = 0; i < 4; ++i)
            #pragma unroll
            for (int j = 0; j < 8; ++j) acc[i][j] = 0.f;
        for (int m0 = 0; m0 < 64; m0 += 4) {
            float p4[4][4];
            #pragma unroll
            for (int i = 0; i < 4; ++i) {
                const float4 u = ld4s(&sa[(h * 64 + n0 + 16 * i) * 68 + m0]);
                p4[i][0] = u.x; p4[i][1] = u.y; p4[i][2] = u.z; p4[i][3] = u.w;
            }
            #pragma unroll
            for (int mi = 0; mi < 4; ++mi) {
                const float4 v0 = ld4s(&qk[(m0 + mi) * 292 + vofs]);
                const float4 v1 = ld4s(&qk[(m0 + mi) * 292 + vofs + 4]);
                #pragma unroll
                for (int i = 0; i < 4; ++i) {
                    const float p = p4[i][mi];
                    acc[i][0] += p * v0.x; acc[i][1] += p * v0.y;
                    acc[i][2] += p * v0.z; acc[i][3] += p * v0.w;
                    acc[i][4] += p * v1.x; acc[i][5] += p * v1.y;
                    acc[i][6] += p * v1.z; acc[i][7] += p * v1.w;
                }
            }
        }
        #pragma unroll
        for (int i = 0; i < 4; ++i) {
            const int base = (n0 + 16 * i) * 104 + h * 16 + d0;
            #pragma unroll
            for (int j = 0; j < 4; ++j) {
                unsigned short h0, l0, h1, l1;
                bf16_split(acc[i][2 * j], h0, l0);
                bf16_split(acc[i][2 * j + 1], h1, l1);
                *(u32*)(smc + AT_XH + (base + 2 * j) * 2) = pack2(h0, h1);
                *(u32*)(smc + AT_XL + (base + 2 * j) * 2) = pack2(l0, l1);
            }
        }
    }
    __syncthreads();

    // ---- proj GEMM via mma: C[64][96]. warp = (m-tile wid&3, n-half wid>>2) ----
    {
        const int m0 = (wid & 3) * 16;
        const int nb = (wid >> 2) * 48;
        float acc[6][4];
        #pragma unroll
        for (int nt = 0; nt < 6; ++nt)
            #pragma unroll
            for (int q = 0; q < 4; ++q) acc[nt][q] = 0.f;
        #pragma unroll
        for (int ks = 0; ks < 6; ++ks) {
            const int ra = (m0 + lg) * 104 + ks * 16 + tg * 2;
            const u32 ah0 = *(u32*)(smc + AT_XH + ra * 2);
            const u32 ah1 = *(u32*)(smc + AT_XH + (ra + 8 * 104) * 2);
            const u32 ah2 = *(u32*)(smc + AT_XH + (ra + 8) * 2);
            const u32 ah3 = *(u32*)(smc + AT_XH + (ra + 8 * 104 + 8) * 2);
            const u32 al0 = *(u32*)(smc + AT_XL + ra * 2);
            const u32 al1 = *(u32*)(smc + AT_XL + (ra + 8 * 104) * 2);
            const u32 al2 = *(u32*)(smc + AT_XL + (ra + 8) * 2);
            const u32 al3 = *(u32*)(smc + AT_XL + (ra + 8 * 104 + 8) * 2);
            #pragma unroll
            for (int nt = 0; nt < 6; ++nt) {
                const int bi = (nb + nt * 8 + lg) * 48 + ks * 8 + tg;
                const u32 bh0 = g_ph[bi], bh1 = g_ph[bi + 4];
                const u32 bl0 = g_pl[bi], bl1 = g_pl[bi + 4];
                mma_bf16(acc[nt], ah0, ah1, ah2, ah3, bh0, bh1);
                mma_bf16(acc[nt], ah0, ah1, ah2, ah3, bl0, bl1);
                mma_bf16(acc[nt], al0, al1, al2, al3, bh0, bh1);
            }
        }
        #pragma unroll
        for (int nt = 0; nt < 6; ++nt) {
            const int n0 = nb + nt * 8 + tg * 2;
            const float b0v = proj_b[n0], b1v = proj_b[n0 + 1];
            *(float2*)&g_y[(win * 64 + m0 + lg) * 96 + n0] =
                make_float2(acc[nt][0] + b0v, acc[nt][1] + b1v);
            *(float2*)&g_y[(win * 64 + m0 + lg + 8) * 96 + n0] =
                make_float2(acc[nt][2] + b0v, acc[nt][3] + b1v);
        }
    }
}

// ============================================================================
// Kernel D: window reverse + un-shift + residual + LayerNorm2 -> transposed out
// ============================================================================
__global__ void k_res_ln2(const float* __restrict__ x,
                          const float* __restrict__ n2w,
                          const float* __restrict__ n2b) {
    __shared__ float s[CC * 65];
    const int h = blockIdx.y;
    const int w0 = blockIdx.x * 64;
    const int t = threadIdx.x;

    #pragma unroll 4
    for (int c = 0; c < CC; ++c)
        s[c * 65 + t] = x[c * HWSZ + h * WW + w0 + t];
    __syncthreads();

    for (int idx = t; idx < 64 * CC; idx += 64) {
        const int tt = idx / CC, c = idx - tt * CC;
        const int wp = w0 + tt;
        const int hs = (h - SHIFT) & (HH - 1);
        const int ws = (wp - SHIFT) & (WW - 1);
        const int base = (((hs >> 3) * 64 + (ws >> 3)) * NTOK + ((hs & 7) << 3) + (ws & 7)) * CC;
        s[c * 65 + tt] += g_y[base + c];
    }
    __syncthreads();

    float mu = 0.f;
    #pragma unroll 8
    for (int c = 0; c < CC; ++c) mu += s[c * 65 + t];
    mu *= (1.0f / CC);
    float var = 0.f;
    #pragma unroll 8
    for (int c = 0; c < CC; ++c) { float d = s[c * 65 + t] - mu; var += d * d; }
    var *= (1.0f / CC);
    const float rstd = rsqrtf(var + EPS);

    const int p = h * WW + w0 + t;
    #pragma unroll 4
    for (int c = 0; c < CC; ++c) {
        const float v = s[c * 65 + t];
        g_x1T[c * HWSZ + p] = v;
        g_hnT[c * HWSZ + p] = (v - mu) * rstd * n2w[c] + n2b[c];
    }
}

// ============================================================================
// Kernel E: MLP via mma.sync bf16 split. Weights pre-split in global (direct LDG).
// 2048 CTAs x 256 threads (8 warps), 128 pixels per CTA.
// smem: A1 hi @0 / lo @26624 (128x104 bf16); A2 hi @53248 / lo @88064 (128x136)
// ============================================================================
#define OFF_A1H 0
#define OFF_A1L 26624
#define OFF_A2H 53248
#define OFF_A2L 88064
#define SMEM_MLP 122880

__global__ __launch_bounds__(256, 1)
void k_mlp_mma(const float* __restrict__ fc1_b,
               const float* __restrict__ fc2_b,
               float* __restrict__ out) {
    extern __shared__ char smc[];
    const int tid = threadIdx.x;
    const int wid = tid >> 5;
    const int lane = tid & 31;
    const int lg = lane >> 2;      // 0..7
    const int tg = lane & 3;       // 0..3
    const int p0 = blockIdx.x * 128;
    const int m0 = wid * 16;       // warp's M rows

    // ---- stage A1 = LN2 output as bf16 hi/lo, [tok][c], stride 104 ----
    for (int i = tid; i < 128 * 48; i += 256) {
        const int p = i & 127;
        const int c0 = (i >> 7) << 1;
        const float v0 = g_hnT[c0 * HWSZ + p0 + p];
        const float v1 = g_hnT[(c0 + 1) * HWSZ + p0 + p];
        unsigned short h0, l0, h1, l1;
        bf16_split(v0, h0, l0);
        bf16_split(v1, h1, l1);
        *(u32*)(smc + OFF_A1H + (p * 104 + c0) * 2) = pack2(h0, h1);
        *(u32*)(smc + OFF_A1L + (p * 104 + c0) * 2) = pack2(l0, l1);
    }
    __syncthreads();

    float acc2[12][4];
    #pragma unroll
    for (int nt = 0; nt < 12; ++nt)
        #pragma unroll
        for (int q = 0; q < 4; ++q) acc2[nt][q] = 0.f;

    for (int nc = 0; nc < 3; ++nc) {
        // ---- GEMM1 chunk: D1[m0..+15][nc*128..+127] ----
        float acc1[16][4];
        #pragma unroll
        for (int nt = 0; nt < 16; ++nt)
            #pragma unroll
            for (int q = 0; q < 4; ++q) acc1[nt][q] = 0.f;

        #pragma unroll
        for (int ks = 0; ks < 6; ++ks) {
            const int ra = (m0 + lg) * 104 + ks * 16 + tg * 2;
            const u32 ah0 = *(u32*)(smc + OFF_A1H + ra * 2);
            const u32 ah1 = *(u32*)(smc + OFF_A1H + (ra + 8 * 104) * 2);
            const u32 ah2 = *(u32*)(smc + OFF_A1H + (ra + 8) * 2);
            const u32 ah3 = *(u32*)(smc + OFF_A1H + (ra + 8 * 104 + 8) * 2);
            const u32 al0 = *(u32*)(smc + OFF_A1L + ra * 2);
            const u32 al1 = *(u32*)(smc + OFF_A1L + (ra + 8 * 104) * 2);
            const u32 al2 = *(u32*)(smc + OFF_A1L + (ra + 8) * 2);
            const u32 al3 = *(u32*)(smc + OFF_A1L + (ra + 8 * 104 + 8) * 2);
            #pragma unroll
            for (int nt = 0; nt < 16; ++nt) {
                const int bi = (nc * 128 + nt * 8 + lg) * 48 + ks * 8 + tg;
                const u32 bh0 = g_w1h[bi], bh1 = g_w1h[bi + 4];
                const u32 bl0 = g_w1l[bi], bl1 = g_w1l[bi + 4];
                mma_bf16(acc1[nt], ah0, ah1, ah2, ah3, bh0, bh1);
                mma_bf16(acc1[nt], ah0, ah1, ah2, ah3, bl0, bl1);
                mma_bf16(acc1[nt], al0, al1, al2, al3, bh0, bh1);
            }
        }

        // ---- bias + GELU + split -> A2 (own rows, no race with other warps) ----
        #pragma unroll
        for (int nt = 0; nt < 16; ++nt) {
            const int jb = nc * 128 + nt * 8 + tg * 2;
            const float bv0 = fc1_b[jb], bv1 = fc1_b[jb + 1];
            float x0 = acc1[nt][0] + bv0;
            float x1 = acc1[nt][1] + bv1;
            float y0 = acc1[nt][2] + bv0;
            float y1 = acc1[nt][3] + bv1;
            x0 = 0.5f * x0 * (1.0f + erff(x0 * 0.70710678118654752f));
            x1 = 0.5f * x1 * (1.0f + erff(x1 * 0.70710678118654752f));
            y0 = 0.5f * y0 * (1.0f + erff(y0 * 0.70710678118654752f));
            y1 = 0.5f * y1 * (1.0f + erff(y1 * 0.70710678118654752f));
            unsigned short h0, l0, h1, l1;
            const int col = nt * 8 + tg * 2;
            bf16_split(x0, h0, l0); bf16_split(x1, h1, l1);
            *(u32*)(smc + OFF_A2H + ((m0 + lg) * 136 + col) * 2) = pack2(h0, h1);
            *(u32*)(smc + OFF_A2L + ((m0 + lg) * 136 + col) * 2) = pack2(l0, l1);
            bf16_split(y0, h0, l0); bf16_split(y1, h1, l1);
            *(u32*)(smc + OFF_A2H + ((m0 + lg + 8) * 136 + col) * 2) = pack2(h0, h1);
            *(u32*)(smc + OFF_A2L + ((m0 + lg + 8) * 136 + col) * 2) = pack2(l0, l1);
        }
        __syncthreads();   // A2 complete before any warp's GEMM2 reads

        // ---- GEMM2 partial: acc2 += A2 @ W2chunk^T ----
        #pragma unroll
        for (int ks = 0; ks < 8; ++ks) {
            const int ra = (m0 + lg) * 136 + ks * 16 + tg * 2;
            const u32 ah0 = *(u32*)(smc + OFF_A2H + ra * 2);
            const u32 ah1 = *(u32*)(smc + OFF_A2H + (ra + 8 * 136) * 2);
            const u32 ah2 = *(u32*)(smc + OFF_A2H + (ra + 8) * 2);
            const u32 ah3 = *(u32*)(smc + OFF_A2H + (ra + 8 * 136 + 8) * 2);
            const u32 al0 = *(u32*)(smc + OFF_A2L + ra * 2);
            const u32 al1 = *(u32*)(smc + OFF_A2L + (ra + 8 * 136) * 2);
            const u32 al2 = *(u32*)(smc + OFF_A2L + (ra + 8) * 2);
            const u32 al3 = *(u32*)(smc + OFF_A2L + (ra + 8 * 136 + 8) * 2);
            #pragma unroll
            for (int nt = 0; nt < 12; ++nt) {
                const int bi = (nt * 8 + lg) * 192 + nc * 64 + ks * 8 + tg;
                const u32 bh0 = g_w2h[bi], bh1 = g_w2h[bi + 4];
                const u32 bl0 = g_w2l[bi], bl1 = g_w2l[bi + 4];
                mma_bf16(acc2[nt], ah0, ah1, ah2, ah3, bh0, bh1);
                mma_bf16(acc2[nt], ah0, ah1, ah2, ah3, bl0, bl1);
                mma_bf16(acc2[nt], al0, al1, al2, al3, bh0, bh1);
            }
        }
        __syncthreads();   // GEMM2 reads done before next chunk overwrites A2
    }

    // ---- epilogue: + bias + residual -> NCHW out ----
    const int pA = p0 + m0 + lg;
    const int pB = pA + 8;
    #pragma unroll
    for (int nt = 0; nt < 12; ++nt) {
        const int r0c = nt * 8 + tg * 2;
        const float b0v = fc2_b[r0c], b1v = fc2_b[r0c + 1];
        out[r0c * HWSZ + pA]       = acc2[nt][0] + b0v + g_x1T[r0c * HWSZ + pA];
        out[(r0c + 1) * HWSZ + pA] = acc2[nt][1] + b1v + g_x1T[(r0c + 1) * HWSZ + pA];
        out[r0c * HWSZ + pB]       = acc2[nt][2] + b0v + g_x1T[r0c * HWSZ + pB];
        out[(r0c + 1) * HWSZ + pB] = acc2[nt][3] + b1v + g_x1T[(r0c + 1) * HWSZ + pB];
    }
}

// ============================================================================
extern "C" void kernel_launch(void* const* d_in, const int* in_sizes, int n_in,
                              void* d_out, int out_size) {
    const float* x      = (const float*)d_in[0];
    const float* n1w    = (const float*)d_in[1];
    const float* n1b    = (const float*)d_in[2];
    const float* qkv_w  = (const float*)d_in[3];
    const float* qkv_b  = (const float*)d_in[4];
    const float* rpb    = (const float*)d_in[5];
    const float* proj_w = (const float*)d_in[6];
    const float* proj_b = (const float*)d_in[7];
    const float* n2w    = (const float*)d_in[8];
    const float* n2b    = (const float*)d_in[9];
    const float* fc1_w  = (const float*)d_in[10];
    const float* fc1_b  = (const float*)d_in[11];
    const float* fc2_w  = (const float*)d_in[12];
    const float* fc2_b  = (const float*)d_in[13];
    float* out = (float*)d_out;

    cudaFuncSetAttribute(k_attn,    cudaFuncAttributeMaxDynamicSharedMemorySize, SMEM_ATTN);
    cudaFuncSetAttribute(k_mlp_mma, cudaFuncAttributeMaxDynamicSharedMemorySize, SMEM_MLP);

    k_split_w<<<216, 256>>>(qkv_w, proj_w, fc1_w, fc2_w);
    k_ln1_window<<<dim3(8, 512), 64>>>(x, n1w, n1b);
    k_attn<<<NWIN, 256, SMEM_ATTN>>>(qkv_b, rpb, proj_b);
    k_res_ln2<<<dim3(8, 512), 64>>>(x, n2w, n2b);
    k_mlp_mma<<<HWSZ / 128, 256, SMEM_MLP>>>(fc1_b, fc2_b, out);
}

// round 15
// speedup vs baseline: 1.5335x; 1.5335x over previous
#include <cuda_runtime.h>
#include <cuda_bf16.h>
#include <math.h>

// ---------------- problem constants ----------------
#define HH 512
#define WW 512
#define CC 96
#define HWSZ (HH * WW)            // 262144
#define WIN 8
#define SHIFT 4
#define NTOK 64
#define NWIN 4096
#define HEADS 6
#define HD 16
#define MLPH 384
#define EPS 1e-5f

typedef unsigned int u32;
typedef unsigned long long u64b;

__device__ __forceinline__ float4 ld4s(const float* p) {
    return *reinterpret_cast<const float4*>(p);
}

// ---------------- scratch ----------------
__device__ float g_xw[NWIN * NTOK * CC];   // LN1'd, shifted, windowed tokens [win][tok][96]
__device__ float g_y[NWIN * NTOK * CC];    // attention+proj output [win][tok][96]
__device__ float g_x1T[CC * HWSZ];         // residual-1, TRANSPOSED [c][p]
__device__ float g_hnT[CC * HWSZ];         // LN2 output,  TRANSPOSED [c][p]

// ---------------- fragment-major pre-split weights ----------------
// One u64 per (n-tile, k-step, lane): lo32 = b0 (bf16 pair k=2kp,2kp+1),
// hi32 = b1 (pair k=2kp+8,2kp+9), kp = ks*8 + (lane&3), row = ntile*8 + (lane>>2).
// Lanes contiguous -> every fragment load is one coalesced LDG.64.
#define QF_N  6912    // qkv:  36 ntiles * 6 ks * 32
#define PF_N  2304    // proj: 12 * 6 * 32
#define W1F_N 9216    // fc1:  48 * 6 * 32
#define W2F_N 9216    // fc2:  12 * 24 * 32
__device__ u64b g_qf_h[QF_N],  g_qf_l[QF_N];
__device__ u64b g_pf_h[PF_N],  g_pf_l[PF_N];
__device__ u64b g_w1f_h[W1F_N], g_w1f_l[W1F_N];
__device__ u64b g_w2f_h[W2F_N], g_w2f_l[W2F_N];

// ---------------- bf16 split helpers ----------------
__device__ __forceinline__ void bf16_split(float v, unsigned short& h, unsigned short& l) {
    __nv_bfloat16 hb = __float2bfloat16(v);
    __nv_bfloat16 lb = __float2bfloat16(v - __bfloat162float(hb));
    h = __bfloat16_as_ushort(hb);
    l = __bfloat16_as_ushort(lb);
}
__device__ __forceinline__ u32 pack2(unsigned short a, unsigned short b) {
    return (u32)a | ((u32)b << 16);
}

// mma.sync m16n8k16 bf16 (baseline sm_80+; valid for plain sm_103 target)
__device__ __forceinline__ void mma_bf16(float* c, u32 a0, u32 a1, u32 a2, u32 a3,
                                         u32 b0, u32 b1) {
    asm volatile(
        "mma.sync.aligned.m16n8k16.row.col.f32.bf16.bf16.f32 "
        "{%0,%1,%2,%3}, {%4,%5,%6,%7}, {%8,%9}, {%0,%1,%2,%3};"
        : "+f"(c[0]), "+f"(c[1]), "+f"(c[2]), "+f"(c[3])
        : "r"(a0), "r"(a1), "r"(a2), "r"(a3), "r"(b0), "r"(b1));
}
// 3-term split mma: hi*hi + hi*lo + lo*hi (fp32-grade accuracy)
__device__ __forceinline__ void mma3(float* c,
                                     u32 ah0, u32 ah1, u32 ah2, u32 ah3,
                                     u32 al0, u32 al1, u32 al2, u32 al3,
                                     u64b bh, u64b bl) {
    const u32 bh0 = (u32)bh, bh1 = (u32)(bh >> 32);
    const u32 bl0 = (u32)bl, bl1 = (u32)(bl >> 32);
    mma_bf16(c, ah0, ah1, ah2, ah3, bh0, bh1);
    mma_bf16(c, ah0, ah1, ah2, ah3, bl0, bl1);
    mma_bf16(c, al0, al1, al2, al3, bh0, bh1);
}

// ============================================================================
// Kernel W: one-time split of all weights into fragment-major bf16 hi/lo u64.
// ============================================================================
__device__ __forceinline__ void split_slot(const float* __restrict__ W, int K,
                                           int ntile, int ks, int lane,
                                           u64b& hv, u64b& lv) {
    const int row = ntile * 8 + (lane >> 2);
    const int base = row * K + 2 * (ks * 8 + (lane & 3));
    unsigned short h0, l0, h1, l1, h2, l2, h3, l3;
    bf16_split(W[base], h0, l0);
    bf16_split(W[base + 1], h1, l1);
    bf16_split(W[base + 8], h2, l2);
    bf16_split(W[base + 9], h3, l3);
    hv = (u64b)pack2(h0, h1) | ((u64b)pack2(h2, h3) << 32);
    lv = (u64b)pack2(l0, l1) | ((u64b)pack2(l2, l3) << 32);
}

__global__ void k_split_w(const float* __restrict__ qkv_w, const float* __restrict__ proj_w,
                          const float* __restrict__ fc1_w, const float* __restrict__ fc2_w) {
    const int i = blockIdx.x * 256 + threadIdx.x;
    u64b hv, lv;
    if (i < QF_N) {
        const int s = i;
        split_slot(qkv_w, 96, s / 192, (s / 32) % 6, s & 31, hv, lv);
        g_qf_h[s] = hv; g_qf_l[s] = lv;
    } else if (i < QF_N + PF_N) {
        const int s = i - QF_N;
        split_slot(proj_w, 96, s / 192, (s / 32) % 6, s & 31, hv, lv);
        g_pf_h[s] = hv; g_pf_l[s] = lv;
    } else if (i < QF_N + PF_N + W1F_N) {
        const int s = i - QF_N - PF_N;
        split_slot(fc1_w, 96, s / 192, (s / 32) % 6, s & 31, hv, lv);
        g_w1f_h[s] = hv; g_w1f_l[s] = lv;
    } else if (i < QF_N + PF_N + W1F_N + W2F_N) {
        const int s = i - QF_N - PF_N - W1F_N;
        split_slot(fc2_w, 384, s / 768, (s / 32) % 24, s & 31, hv, lv);
        g_w2f_h[s] = hv; g_w2f_l[s] = lv;
    }
}

// ============================================================================
// Kernel A: NCHW read + LayerNorm1 + cyclic shift + window partition
// ============================================================================
__global__ void k_ln1_window(const float* __restrict__ x,
                             const float* __restrict__ n1w,
                             const float* __restrict__ n1b) {
    __shared__ float s[CC * 65];
    const int h = blockIdx.y;
    const int w0 = blockIdx.x * 64;
    const int t = threadIdx.x;

    #pragma unroll 4
    for (int c = 0; c < CC; ++c)
        s[c * 65 + t] = x[c * HWSZ + h * WW + w0 + t];
    __syncthreads();

    float mu = 0.f;
    #pragma unroll 8
    for (int c = 0; c < CC; ++c) mu += s[c * 65 + t];
    mu *= (1.0f / CC);
    float var = 0.f;
    #pragma unroll 8
    for (int c = 0; c < CC; ++c) { float d = s[c * 65 + t] - mu; var += d * d; }
    var *= (1.0f / CC);
    const float rstd = rsqrtf(var + EPS);
    #pragma unroll 8
    for (int c = 0; c < CC; ++c)
        s[c * 65 + t] = (s[c * 65 + t] - mu) * rstd * n1w[c] + n1b[c];
    __syncthreads();

    for (int idx = t; idx < 64 * CC; idx += 64) {
        const int tt = idx / CC, c = idx - tt * CC;
        const int wp = w0 + tt;
        const int hs = (h - SHIFT) & (HH - 1);
        const int ws = (wp - SHIFT) & (WW - 1);
        const int win = (hs >> 3) * 64 + (ws >> 3);
        const int tok = ((hs & 7) << 3) + (ws & 7);
        g_xw[(win * NTOK + tok) * CC + c] = s[c * 65 + tt];
    }
}

// ============================================================================
// Kernel C: per-window attention. qkv + proj via mma (fragment-major B),
// S/softmax/PV scalar fp32.
// smem (bytes): [0,13312) X/PO hi (64x104 bf16) | [13312,26624) lo
//               [26624,101376) qk fp32 [64][292] | [101376,205824) sa [6][64][68]
// ============================================================================
#define AT_XH 0
#define AT_XL 13312
#define SMEM_ATTN 205824

__global__ __launch_bounds__(256, 1)
void k_attn(const float* __restrict__ qkv_b,
            const float* __restrict__ rpb,
            const float* __restrict__ proj_b) {
    extern __shared__ char smc[];
    float* qk = (float*)(smc + 26624);    // [64][292]: q 0..95, k 96..191, v 192..287
    float* sa = (float*)(smc + 101376);   // [6][64][68]
    __shared__ int rg[64];

    const int win = blockIdx.x;
    const int tid = threadIdx.x;
    const int wid = tid >> 5;
    const int lane = tid & 31;
    const int lg = lane >> 2;      // 0..7
    const int tg = lane & 3;       // 0..3
    const int wi = win >> 6, wj = win & 63;

    // ---- stage X: split LN1'd window tokens to bf16 hi/lo ----
    const float* src = g_xw + win * (NTOK * CC);
    for (int i = tid; i < 64 * 48; i += 256) {
        const int tok = i / 48, k2 = i - tok * 48;
        unsigned short h0, l0, h1, l1;
        bf16_split(src[tok * 96 + 2 * k2], h0, l0);
        bf16_split(src[tok * 96 + 2 * k2 + 1], h1, l1);
        const int off = (tok * 104 + 2 * k2) * 2;
        *(u32*)(smc + AT_XH + off) = pack2(h0, h1);
        *(u32*)(smc + AT_XL + off) = pack2(l0, l1);
    }
    if (tid < 64) {
        const int r1 = tid >> 3, c1 = tid & 7;
        const int a = (wi == 63) ? (r1 < SHIFT ? 1 : 2) : 0;
        const int b = (wj == 63) ? (c1 < SHIFT ? 1 : 2) : 0;
        rg[tid] = a * 3 + b;
    }
    __syncthreads();

    // ---- qkv GEMM via mma: C[64][288]. warp = (m-tile wid&3, n-half wid>>2) ----
    {
        const int m0 = (wid & 3) * 16;
        const int tb = (wid >> 2) * 18;    // fragment n-tile base
        float acc[18][4];
        #pragma unroll
        for (int nt = 0; nt < 18; ++nt)
            #pragma unroll
            for (int q = 0; q < 4; ++q) acc[nt][q] = 0.f;
        #pragma unroll
        for (int ks = 0; ks < 6; ++ks) {
            const int ra = (m0 + lg) * 104 + ks * 16 + tg * 2;
            const u32 ah0 = *(u32*)(smc + AT_XH + ra * 2);
            const u32 ah1 = *(u32*)(smc + AT_XH + (ra + 8 * 104) * 2);
            const u32 ah2 = *(u32*)(smc + AT_XH + (ra + 8) * 2);
            const u32 ah3 = *(u32*)(smc + AT_XH + (ra + 8 * 104 + 8) * 2);
            const u32 al0 = *(u32*)(smc + AT_XL + ra * 2);
            const u32 al1 = *(u32*)(smc + AT_XL + (ra + 8 * 104) * 2);
            const u32 al2 = *(u32*)(smc + AT_XL + (ra + 8) * 2);
            const u32 al3 = *(u32*)(smc + AT_XL + (ra + 8 * 104 + 8) * 2);
            #pragma unroll
            for (int nt = 0; nt < 18; ++nt) {
                const int fi = ((tb + nt) * 6 + ks) * 32 + lane;
                mma3(acc[nt], ah0, ah1, ah2, ah3, al0, al1, al2, al3,
                     g_qf_h[fi], g_qf_l[fi]);
            }
        }
        const int nb = (wid >> 2) * 144;
        #pragma unroll
        for (int nt = 0; nt < 18; ++nt) {
            const int n0 = nb + nt * 8 + tg * 2;
            const float b0v = qkv_b[n0], b1v = qkv_b[n0 + 1];
            *(float2*)&qk[(m0 + lg) * 292 + n0] =
                make_float2(acc[nt][0] + b0v, acc[nt][1] + b1v);
            *(float2*)&qk[(m0 + lg + 8) * 292 + n0] =
                make_float2(acc[nt][2] + b0v, acc[nt][3] + b1v);
        }
    }
    __syncthreads();

    // ---- S = q k^T * scale + bias + mask (scalar, all heads) ----
    for (int gg = tid; gg < 768; gg += 256) {
        const int h = gg >> 7;
        const int rem = gg & 127;
        const int n0 = rem & 15;
        const int m0 = (rem >> 4) << 3;
        const int qo = h * 16, ko = 96 + h * 16;
        float qv[4][16];
        #pragma unroll
        for (int i = 0; i < 4; ++i) {
            #pragma unroll
            for (int k = 0; k < 4; ++k) {
                const float4 v = ld4s(&qk[(n0 + 16 * i) * 292 + qo + 4 * k]);
                qv[i][4 * k] = v.x; qv[i][4 * k + 1] = v.y;
                qv[i][4 * k + 2] = v.z; qv[i][4 * k + 3] = v.w;
            }
        }
        float acc[4][8];
        #pragma unroll
        for (int i = 0; i < 4; ++i)
            #pragma unroll
            for (int j = 0; j < 8; ++j) acc[i][j] = 0.f;
        #pragma unroll
        for (int j = 0; j < 8; ++j) {
            float kv[16];
            #pragma unroll
            for (int k = 0; k < 4; ++k) {
                const float4 v = ld4s(&qk[(m0 + j) * 292 + ko + 4 * k]);
                kv[4 * k] = v.x; kv[4 * k + 1] = v.y;
                kv[4 * k + 2] = v.z; kv[4 * k + 3] = v.w;
            }
            #pragma unroll
            for (int i = 0; i < 4; ++i) {
                float a = 0.f;
                #pragma unroll
                for (int d = 0; d < 16; ++d) a += qv[i][d] * kv[d];
                acc[i][j] = a;
            }
        }
        #pragma unroll
        for (int i = 0; i < 4; ++i) {
            const int n = n0 + 16 * i;
            const int r1 = n >> 3, c1 = n & 7;
            const int rgn = rg[n];
            float vo[8];
            #pragma unroll
            for (int j = 0; j < 8; ++j) {
                const int m = m0 + j;
                const int r2 = m >> 3, c2 = m & 7;
                float s = acc[i][j] * 0.25f
                        + rpb[((r1 - r2 + 7) * 15 + (c1 - c2 + 7)) * HEADS + h];
                if (rgn != rg[m]) s -= 100.0f;
                vo[j] = s;
            }
            *reinterpret_cast<float4*>(&sa[(h * 64 + n) * 68 + m0]) =
                make_float4(vo[0], vo[1], vo[2], vo[3]);
            *reinterpret_cast<float4*>(&sa[(h * 64 + n) * 68 + m0 + 4]) =
                make_float4(vo[4], vo[5], vo[6], vo[7]);
        }
    }
    __syncthreads();

    // ---- softmax: 384 rows ----
    for (int r = tid; r < 384; r += 256) {
        float* row = sa + r * 68;
        float mx = -1e30f;
        #pragma unroll
        for (int m = 0; m < 64; m += 4) {
            float4 v = *reinterpret_cast<float4*>(&row[m]);
            mx = fmaxf(mx, fmaxf(fmaxf(v.x, v.y), fmaxf(v.z, v.w)));
        }
        float sum = 0.f;
        #pragma unroll
        for (int m = 0; m < 64; m += 4) {
            float4 v = *reinterpret_cast<float4*>(&row[m]);
            v.x = __expf(v.x - mx); v.y = __expf(v.y - mx);
            v.z = __expf(v.z - mx); v.w = __expf(v.w - mx);
            sum += v.x + v.y + v.z + v.w;
            *reinterpret_cast<float4*>(&row[m]) = v;
        }
        const float inv = 1.0f / sum;
        #pragma unroll
        for (int m = 0; m < 64; m += 4) {
            float4 v = *reinterpret_cast<float4*>(&row[m]);
            v.x *= inv; v.y *= inv; v.z *= inv; v.w *= inv;
            *reinterpret_cast<float4*>(&row[m]) = v;
        }
    }
    __syncthreads();

    // ---- PV (scalar) -> write output pre-split bf16 hi/lo into X region ----
    if (tid < 192) {
        const int h = tid / 32;
        const int rem = tid & 31;
        const int n0 = rem & 15;
        const int d0 = (rem >> 4) << 3;
        const int vofs = 192 + h * 16 + d0;
        float acc[4][8];
        #pragma unroll
        for (int i = 0; i < 4; ++i)
            #pragma unroll
            for (int j = 0; j < 8; ++j) acc[i][j] = 0.f;
        for (int m0 = 0; m0 < 64; m0 += 4) {
            float p4[4][4];
            #pragma unroll
            for (int i = 0; i < 4; ++i) {
                const float4 u = ld4s(&sa[(h * 64 + n0 + 16 * i) * 68 + m0]);
                p4[i][0] = u.x; p4[i][1] = u.y; p4[i][2] = u.z; p4[i][3] = u.w;
            }
            #pragma unroll
            for (int mi = 0; mi < 4; ++mi) {
                const float4 v0 = ld4s(&qk[(m0 + mi) * 292 + vofs]);
                const float4 v1 = ld4s(&qk[(m0 + mi) * 292 + vofs + 4]);
                #pragma unroll
                for (int i = 0; i < 4; ++i) {
                    const float p = p4[i][mi];
                    acc[i][0] += p * v0.x; acc[i][1] += p * v0.y;
                    acc[i][2] += p * v0.z; acc[i][3] += p * v0.w;
                    acc[i][4] += p * v1.x; acc[i][5] += p * v1.y;
                    acc[i][6] += p * v1.z; acc[i][7] += p * v1.w;
                }
            }
        }
        #pragma unroll
        for (int i = 0; i < 4; ++i) {
            const int base = (n0 + 16 * i) * 104 + h * 16 + d0;
            #pragma unroll
            for (int j = 0; j < 4; ++j) {
                unsigned short h0, l0, h1, l1;
                bf16_split(acc[i][2 * j], h0, l0);
                bf16_split(acc[i][2 * j + 1], h1, l1);
                *(u32*)(smc + AT_XH + (base + 2 * j) * 2) = pack2(h0, h1);
                *(u32*)(smc + AT_XL + (base + 2 * j) * 2) = pack2(l0, l1);
            }
        }
    }
    __syncthreads();

    // ---- proj GEMM via mma: C[64][96] ----
    {
        const int m0 = (wid & 3) * 16;
        const int tb = (wid >> 2) * 6;
        float acc[6][4];
        #pragma unroll
        for (int nt = 0; nt < 6; ++nt)
            #pragma unroll
            for (int q = 0; q < 4; ++q) acc[nt][q] = 0.f;
        #pragma unroll
        for (int ks = 0; ks < 6; ++ks) {
            const int ra = (m0 + lg) * 104 + ks * 16 + tg * 2;
            const u32 ah0 = *(u32*)(smc + AT_XH + ra * 2);
            const u32 ah1 = *(u32*)(smc + AT_XH + (ra + 8 * 104) * 2);
            const u32 ah2 = *(u32*)(smc + AT_XH + (ra + 8) * 2);
            const u32 ah3 = *(u32*)(smc + AT_XH + (ra + 8 * 104 + 8) * 2);
            const u32 al0 = *(u32*)(smc + AT_XL + ra * 2);
            const u32 al1 = *(u32*)(smc + AT_XL + (ra + 8 * 104) * 2);
            const u32 al2 = *(u32*)(smc + AT_XL + (ra + 8) * 2);
            const u32 al3 = *(u32*)(smc + AT_XL + (ra + 8 * 104 + 8) * 2);
            #pragma unroll
            for (int nt = 0; nt < 6; ++nt) {
                const int fi = ((tb + nt) * 6 + ks) * 32 + lane;
                mma3(acc[nt], ah0, ah1, ah2, ah3, al0, al1, al2, al3,
                     g_pf_h[fi], g_pf_l[fi]);
            }
        }
        const int nb = (wid >> 2) * 48;
        #pragma unroll
        for (int nt = 0; nt < 6; ++nt) {
            const int n0 = nb + nt * 8 + tg * 2;
            const float b0v = proj_b[n0], b1v = proj_b[n0 + 1];
            *(float2*)&g_y[(win * 64 + m0 + lg) * 96 + n0] =
                make_float2(acc[nt][0] + b0v, acc[nt][1] + b1v);
            *(float2*)&g_y[(win * 64 + m0 + lg + 8) * 96 + n0] =
                make_float2(acc[nt][2] + b0v, acc[nt][3] + b1v);
        }
    }
}

// ============================================================================
// Kernel D: window reverse + un-shift + residual + LayerNorm2 -> transposed out
// ============================================================================
__global__ void k_res_ln2(const float* __restrict__ x,
                          const float* __restrict__ n2w,
                          const float* __restrict__ n2b) {
    __shared__ float s[CC * 65];
    const int h = blockIdx.y;
    const int w0 = blockIdx.x * 64;
    const int t = threadIdx.x;

    #pragma unroll 4
    for (int c = 0; c < CC; ++c)
        s[c * 65 + t] = x[c * HWSZ + h * WW + w0 + t];
    __syncthreads();

    for (int idx = t; idx < 64 * CC; idx += 64) {
        const int tt = idx / CC, c = idx - tt * CC;
        const int wp = w0 + tt;
        const int hs = (h - SHIFT) & (HH - 1);
        const int ws = (wp - SHIFT) & (WW - 1);
        const int base = (((hs >> 3) * 64 + (ws >> 3)) * NTOK + ((hs & 7) << 3) + (ws & 7)) * CC;
        s[c * 65 + tt] += g_y[base + c];
    }
    __syncthreads();

    float mu = 0.f;
    #pragma unroll 8
    for (int c = 0; c < CC; ++c) mu += s[c * 65 + t];
    mu *= (1.0f / CC);
    float var = 0.f;
    #pragma unroll 8
    for (int c = 0; c < CC; ++c) { float d = s[c * 65 + t] - mu; var += d * d; }
    var *= (1.0f / CC);
    const float rstd = rsqrtf(var + EPS);

    const int p = h * WW + w0 + t;
    #pragma unroll 4
    for (int c = 0; c < CC; ++c) {
        const float v = s[c * 65 + t];
        g_x1T[c * HWSZ + p] = v;
        g_hnT[c * HWSZ + p] = (v - mu) * rstd * n2w[c] + n2b[c];
    }
}

// ============================================================================
// Kernel E: MLP via mma.sync bf16 split; fragment-major B from global (LDG.64).
// 2048 CTAs x 256 threads (8 warps), 128 pixels per CTA.
// smem: A1 hi @0 / lo @26624 (128x104 bf16); A2 hi @53248 / lo @88064 (128x136)
// ============================================================================
#define OFF_A1H 0
#define OFF_A1L 26624
#define OFF_A2H 53248
#define OFF_A2L 88064
#define SMEM_MLP 122880

__global__ __launch_bounds__(256, 1)
void k_mlp_mma(const float* __restrict__ fc1_b,
               const float* __restrict__ fc2_b,
               float* __restrict__ out) {
    extern __shared__ char smc[];
    const int tid = threadIdx.x;
    const int wid = tid >> 5;
    const int lane = tid & 31;
    const int lg = lane >> 2;      // 0..7
    const int tg = lane & 3;       // 0..3
    const int p0 = blockIdx.x * 128;
    const int m0 = wid * 16;       // warp's M rows

    // ---- stage A1 = LN2 output as bf16 hi/lo, [tok][c], stride 104 ----
    for (int i = tid; i < 128 * 48; i += 256) {
        const int p = i & 127;
        const int c0 = (i >> 7) << 1;
        const float v0 = g_hnT[c0 * HWSZ + p0 + p];
        const float v1 = g_hnT[(c0 + 1) * HWSZ + p0 + p];
        unsigned short h0, l0, h1, l1;
        bf16_split(v0, h0, l0);
        bf16_split(v1, h1, l1);
        *(u32*)(smc + OFF_A1H + (p * 104 + c0) * 2) = pack2(h0, h1);
        *(u32*)(smc + OFF_A1L + (p * 104 + c0) * 2) = pack2(l0, l1);
    }
    __syncthreads();

    float acc2[12][4];
    #pragma unroll
    for (int nt = 0; nt < 12; ++nt)
        #pragma unroll
        for (int q = 0; q < 4; ++q) acc2[nt][q] = 0.f;

    for (int nc = 0; nc < 3; ++nc) {
        // ---- GEMM1 chunk: D1[m0..+15][nc*128..+127] ----
        float acc1[16][4];
        #pragma unroll
        for (int nt = 0; nt < 16; ++nt)
            #pragma unroll
            for (int q = 0; q < 4; ++q) acc1[nt][q] = 0.f;

        #pragma unroll
        for (int ks = 0; ks < 6; ++ks) {
            const int ra = (m0 + lg) * 104 + ks * 16 + tg * 2;
            const u32 ah0 = *(u32*)(smc + OFF_A1H + ra * 2);
            const u32 ah1 = *(u32*)(smc + OFF_A1H + (ra + 8 * 104) * 2);
            const u32 ah2 = *(u32*)(smc + OFF_A1H + (ra + 8) * 2);
            const u32 ah3 = *(u32*)(smc + OFF_A1H + (ra + 8 * 104 + 8) * 2);
            const u32 al0 = *(u32*)(smc + OFF_A1L + ra * 2);
            const u32 al1 = *(u32*)(smc + OFF_A1L + (ra + 8 * 104) * 2);
            const u32 al2 = *(u32*)(smc + OFF_A1L + (ra + 8) * 2);
            const u32 al3 = *(u32*)(smc + OFF_A1L + (ra + 8 * 104 + 8) * 2);
            #pragma unroll
            for (int nt = 0; nt < 16; ++nt) {
                const int fi = ((nc * 16 + nt) * 6 + ks) * 32 + lane;
                mma3(acc1[nt], ah0, ah1, ah2, ah3, al0, al1, al2, al3,
                     g_w1f_h[fi], g_w1f_l[fi]);
            }
        }

        // ---- bias + GELU + split -> A2 (own rows, no race with other warps) ----
        #pragma unroll
        for (int nt = 0; nt < 16; ++nt) {
            const int jb = nc * 128 + nt * 8 + tg * 2;
            const float bv0 = fc1_b[jb], bv1 = fc1_b[jb + 1];
            float x0 = acc1[nt][0] + bv0;
            float x1 = acc1[nt][1] + bv1;
            float y0 = acc1[nt][2] + bv0;
            float y1 = acc1[nt][3] + bv1;
            x0 = 0.5f * x0 * (1.0f + erff(x0 * 0.70710678118654752f));
            x1 = 0.5f * x1 * (1.0f + erff(x1 * 0.70710678118654752f));
            y0 = 0.5f * y0 * (1.0f + erff(y0 * 0.70710678118654752f));
            y1 = 0.5f * y1 * (1.0f + erff(y1 * 0.70710678118654752f));
            unsigned short h0, l0, h1, l1;
            const int col = nt * 8 + tg * 2;
            bf16_split(x0, h0, l0); bf16_split(x1, h1, l1);
            *(u32*)(smc + OFF_A2H + ((m0 + lg) * 136 + col) * 2) = pack2(h0, h1);
            *(u32*)(smc + OFF_A2L + ((m0 + lg) * 136 + col) * 2) = pack2(l0, l1);
            bf16_split(y0, h0, l0); bf16_split(y1, h1, l1);
            *(u32*)(smc + OFF_A2H + ((m0 + lg + 8) * 136 + col) * 2) = pack2(h0, h1);
            *(u32*)(smc + OFF_A2L + ((m0 + lg + 8) * 136 + col) * 2) = pack2(l0, l1);
        }
        __syncthreads();   // A2 complete before any warp's GEMM2 reads

        // ---- GEMM2 partial: acc2 += A2 @ W2chunk^T ----
        #pragma unroll
        for (int ks = 0; ks < 8; ++ks) {
            const int ra = (m0 + lg) * 136 + ks * 16 + tg * 2;
            const u32 ah0 = *(u32*)(smc + OFF_A2H + ra * 2);
            const u32 ah1 = *(u32*)(smc + OFF_A2H + (ra + 8 * 136) * 2);
            const u32 ah2 = *(u32*)(smc + OFF_A2H + (ra + 8) * 2);
            const u32 ah3 = *(u32*)(smc + OFF_A2H + (ra + 8 * 136 + 8) * 2);
            const u32 al0 = *(u32*)(smc + OFF_A2L + ra * 2);
            const u32 al1 = *(u32*)(smc + OFF_A2L + (ra + 8 * 136) * 2);
            const u32 al2 = *(u32*)(smc + OFF_A2L + (ra + 8) * 2);
            const u32 al3 = *(u32*)(smc + OFF_A2L + (ra + 8 * 136 + 8) * 2);
            #pragma unroll
            for (int nt = 0; nt < 12; ++nt) {
                const int fi = (nt * 24 + nc * 8 + ks) * 32 + lane;
                mma3(acc2[nt], ah0, ah1, ah2, ah3, al0, al1, al2, al3,
                     g_w2f_h[fi], g_w2f_l[fi]);
            }
        }
        __syncthreads();   // GEMM2 reads done before next chunk overwrites A2
    }

    // ---- epilogue: + bias + residual -> NCHW out ----
    const int pA = p0 + m0 + lg;
    const int pB = pA + 8;
    #pragma unroll
    for (int nt = 0; nt < 12; ++nt) {
        const int r0c = nt * 8 + tg * 2;
        const float b0v = fc2_b[r0c], b1v = fc2_b[r0c + 1];
        out[r0c * HWSZ + pA]       = acc2[nt][0] + b0v + g_x1T[r0c * HWSZ + pA];
        out[(r0c + 1) * HWSZ + pA] = acc2[nt][1] + b1v + g_x1T[(r0c + 1) * HWSZ + pA];
        out[r0c * HWSZ + pB]       = acc2[nt][2] + b0v + g_x1T[r0c * HWSZ + pB];
        out[(r0c + 1) * HWSZ + pB] = acc2[nt][3] + b1v + g_x1T[(r0c + 1) * HWSZ + pB];
    }
}

// ============================================================================
extern "C" void kernel_launch(void* const* d_in, const int* in_sizes, int n_in,
                              void* d_out, int out_size) {
    const float* x      = (const float*)d_in[0];
    const float* n1w    = (const float*)d_in[1];
    const float* n1b    = (const float*)d_in[2];
    const float* qkv_w  = (const float*)d_in[3];
    const float* qkv_b  = (const float*)d_in[4];
    const float* rpb    = (const float*)d_in[5];
    const float* proj_w = (const float*)d_in[6];
    const float* proj_b = (const float*)d_in[7];
    const float* n2w    = (const float*)d_in[8];
    const float* n2b    = (const float*)d_in[9];
    const float* fc1_w  = (const float*)d_in[10];
    const float* fc1_b  = (const float*)d_in[11];
    const float* fc2_w  = (const float*)d_in[12];
    const float* fc2_b  = (const float*)d_in[13];
    float* out = (float*)d_out;

    cudaFuncSetAttribute(k_attn,    cudaFuncAttributeMaxDynamicSharedMemorySize, SMEM_ATTN);
    cudaFuncSetAttribute(k_mlp_mma, cudaFuncAttributeMaxDynamicSharedMemorySize, SMEM_MLP);

    k_split_w<<<108, 256>>>(qkv_w, proj_w, fc1_w, fc2_w);
    k_ln1_window<<<dim3(8, 512), 64>>>(x, n1w, n1b);
    k_attn<<<NWIN, 256, SMEM_ATTN>>>(qkv_b, rpb, proj_b);
    k_res_ln2<<<dim3(8, 512), 64>>>(x, n2w, n2b);
    k_mlp_mma<<<HWSZ / 128, 256, SMEM_MLP>>>(fc1_b, fc2_b, out);
}

// round 16
// speedup vs baseline: 1.6679x; 1.0876x over previous
#include <cuda_runtime.h>
#include <cuda_bf16.h>
#include <math.h>

// ---------------- problem constants ----------------
#define HH 512
#define WW 512
#define CC 96
#define HWSZ (HH * WW)            // 262144
#define WIN 8
#define SHIFT 4
#define NTOK 64
#define NWIN 4096
#define HEADS 6
#define HD 16
#define MLPH 384
#define EPS 1e-5f

typedef unsigned int u32;
typedef unsigned long long u64b;

__device__ __forceinline__ float4 ld4s(const float* p) {
    return *reinterpret_cast<const float4*>(p);
}

// ---------------- scratch ----------------
__device__ float g_xw[NWIN * NTOK * CC];   // LN1'd, shifted, windowed tokens [win][tok][96]
__device__ float g_y[NWIN * NTOK * CC];    // attention+proj output [win][tok][96]
__device__ float g_x1T[CC * HWSZ];         // residual-1, TRANSPOSED [c][p]
__device__ float g_hnT[CC * HWSZ];         // LN2 output,  TRANSPOSED [c][p]

// ---------------- fragment-major pre-split weights ----------------
#define QF_N  6912    // qkv:  36 ntiles * 6 ks * 32
#define PF_N  2304    // proj: 12 * 6 * 32
#define W1F_N 9216    // fc1:  48 * 6 * 32
#define W2F_N 9216    // fc2:  12 * 24 * 32
__device__ u64b g_qf_h[QF_N],  g_qf_l[QF_N];
__device__ u64b g_pf_h[PF_N],  g_pf_l[PF_N];
__device__ u64b g_w1f_h[W1F_N], g_w1f_l[W1F_N];
__device__ u64b g_w2f_h[W2F_N], g_w2f_l[W2F_N];

// ---------------- bf16 split helpers ----------------
__device__ __forceinline__ void bf16_split(float v, unsigned short& h, unsigned short& l) {
    __nv_bfloat16 hb = __float2bfloat16(v);
    __nv_bfloat16 lb = __float2bfloat16(v - __bfloat162float(hb));
    h = __bfloat16_as_ushort(hb);
    l = __bfloat16_as_ushort(lb);
}
__device__ __forceinline__ u32 pack2(unsigned short a, unsigned short b) {
    return (u32)a | ((u32)b << 16);
}

// mma.sync m16n8k16 bf16 (baseline sm_80+; valid for plain sm_103 target)
__device__ __forceinline__ void mma_bf16(float* c, u32 a0, u32 a1, u32 a2, u32 a3,
                                         u32 b0, u32 b1) {
    asm volatile(
        "mma.sync.aligned.m16n8k16.row.col.f32.bf16.bf16.f32 "
        "{%0,%1,%2,%3}, {%4,%5,%6,%7}, {%8,%9}, {%0,%1,%2,%3};"
        : "+f"(c[0]), "+f"(c[1]), "+f"(c[2]), "+f"(c[3])
        : "r"(a0), "r"(a1), "r"(a2), "r"(a3), "r"(b0), "r"(b1));
}
__device__ __forceinline__ void mma3(float* c,
                                     u32 ah0, u32 ah1, u32 ah2, u32 ah3,
                                     u32 al0, u32 al1, u32 al2, u32 al3,
                                     u64b bh, u64b bl) {
    const u32 bh0 = (u32)bh, bh1 = (u32)(bh >> 32);
    const u32 bl0 = (u32)bl, bl1 = (u32)(bl >> 32);
    mma_bf16(c, ah0, ah1, ah2, ah3, bh0, bh1);
    mma_bf16(c, ah0, ah1, ah2, ah3, bl0, bl1);
    mma_bf16(c, al0, al1, al2, al3, bh0, bh1);
}

// ============================================================================
// Kernel W: one-time split of all weights into fragment-major bf16 hi/lo u64.
// ============================================================================
__device__ __forceinline__ void split_slot(const float* __restrict__ W, int K,
                                           int ntile, int ks, int lane,
                                           u64b& hv, u64b& lv) {
    const int row = ntile * 8 + (lane >> 2);
    const int base = row * K + 2 * (ks * 8 + (lane & 3));
    unsigned short h0, l0, h1, l1, h2, l2, h3, l3;
    bf16_split(W[base], h0, l0);
    bf16_split(W[base + 1], h1, l1);
    bf16_split(W[base + 8], h2, l2);
    bf16_split(W[base + 9], h3, l3);
    hv = (u64b)pack2(h0, h1) | ((u64b)pack2(h2, h3) << 32);
    lv = (u64b)pack2(l0, l1) | ((u64b)pack2(l2, l3) << 32);
}

__global__ void k_split_w(const float* __restrict__ qkv_w, const float* __restrict__ proj_w,
                          const float* __restrict__ fc1_w, const float* __restrict__ fc2_w) {
    const int i = blockIdx.x * 256 + threadIdx.x;
    u64b hv, lv;
    if (i < QF_N) {
        const int s = i;
        split_slot(qkv_w, 96, s / 192, (s / 32) % 6, s & 31, hv, lv);
        g_qf_h[s] = hv; g_qf_l[s] = lv;
    } else if (i < QF_N + PF_N) {
        const int s = i - QF_N;
        split_slot(proj_w, 96, s / 192, (s / 32) % 6, s & 31, hv, lv);
        g_pf_h[s] = hv; g_pf_l[s] = lv;
    } else if (i < QF_N + PF_N + W1F_N) {
        const int s = i - QF_N - PF_N;
        split_slot(fc1_w, 96, s / 192, (s / 32) % 6, s & 31, hv, lv);
        g_w1f_h[s] = hv; g_w1f_l[s] = lv;
    } else if (i < QF_N + PF_N + W1F_N + W2F_N) {
        const int s = i - QF_N - PF_N - W1F_N;
        split_slot(fc2_w, 384, s / 768, (s / 32) % 24, s & 31, hv, lv);
        g_w2f_h[s] = hv; g_w2f_l[s] = lv;
    }
}

// ============================================================================
// Kernel A: NCHW read + LayerNorm1 + cyclic shift + window partition.
// 256 threads, 256 pixels per block, grid (2, 512). smem 96x260 fp32.
// ============================================================================
#define SMEM_LN (96 * 260 * 4)
__global__ __launch_bounds__(256, 2)
void k_ln1_window(const float* __restrict__ x,
                  const float* __restrict__ n1w,
                  const float* __restrict__ n1b) {
    extern __shared__ float s[];
    const int h = blockIdx.y;
    const int w0 = blockIdx.x * 256;
    const int t = threadIdx.x;

    // coalesced float4 loads; stride-260 smem rows -> conflict-free STS.128
    for (int i = t; i < 96 * 64; i += 256) {
        const int c = i >> 6, q = i & 63;
        *reinterpret_cast<float4*>(&s[c * 260 + 4 * q]) =
            ld4s(&x[c * HWSZ + h * WW + w0 + 4 * q]);
    }
    __syncthreads();

    float mu = 0.f;
    #pragma unroll 8
    for (int c = 0; c < CC; ++c) mu += s[c * 260 + t];
    mu *= (1.0f / CC);
    float var = 0.f;
    #pragma unroll 8
    for (int c = 0; c < CC; ++c) { float d = s[c * 260 + t] - mu; var += d * d; }
    var *= (1.0f / CC);
    const float rstd = rsqrtf(var + EPS);
    #pragma unroll 8
    for (int c = 0; c < CC; ++c)
        s[c * 260 + t] = (s[c * 260 + t] - mu) * rstd * n1w[c] + n1b[c];
    __syncthreads();

    const int hs = (h - SHIFT) & (HH - 1);
    const int winr = (hs >> 3) * 64;
    const int tokr = (hs & 7) << 3;
    for (int i = t; i < 256 * 96; i += 256) {
        const int tt = i / 96, c = i - tt * 96;
        const int ws = (w0 + tt - SHIFT) & (WW - 1);
        g_xw[((winr + (ws >> 3)) * NTOK + tokr + (ws & 7)) * CC + c] = s[c * 260 + tt];
    }
}

// ============================================================================
// Kernel C: per-window attention. qkv + proj via mma (fragment-major B),
// S/softmax/PV scalar fp32. 384 threads (12 warps).
// smem (bytes): [0,13312) X/PO hi (64x104 bf16) | [13312,26624) lo
//               [26624,101376) qk fp32 [64][292] | [101376,205824) sa [6][64][68]
// ============================================================================
#define AT_XH 0
#define AT_XL 13312
#define SMEM_ATTN 205824

__global__ __launch_bounds__(384, 1)
void k_attn(const float* __restrict__ qkv_b,
            const float* __restrict__ rpb,
            const float* __restrict__ proj_b) {
    extern __shared__ char smc[];
    float* qk = (float*)(smc + 26624);    // [64][292]: q 0..95, k 96..191, v 192..287
    float* sa = (float*)(smc + 101376);   // [6][64][68]
    __shared__ int rg[64];

    const int win = blockIdx.x;
    const int tid = threadIdx.x;
    const int wid = tid >> 5;
    const int lane = tid & 31;
    const int lg = lane >> 2;      // 0..7
    const int tg = lane & 3;       // 0..3
    const int wi = win >> 6, wj = win & 63;

    // ---- stage X: split LN1'd window tokens to bf16 hi/lo ----
    const float* src = g_xw + win * (NTOK * CC);
    for (int i = tid; i < 64 * 48; i += 384) {
        const int tok = i / 48, k2 = i - tok * 48;
        unsigned short h0, l0, h1, l1;
        bf16_split(src[tok * 96 + 2 * k2], h0, l0);
        bf16_split(src[tok * 96 + 2 * k2 + 1], h1, l1);
        const int off = (tok * 104 + 2 * k2) * 2;
        *(u32*)(smc + AT_XH + off) = pack2(h0, h1);
        *(u32*)(smc + AT_XL + off) = pack2(l0, l1);
    }
    if (tid < 64) {
        const int r1 = tid >> 3, c1 = tid & 7;
        const int a = (wi == 63) ? (r1 < SHIFT ? 1 : 2) : 0;
        const int b = (wj == 63) ? (c1 < SHIFT ? 1 : 2) : 0;
        rg[tid] = a * 3 + b;
    }
    __syncthreads();

    // ---- qkv GEMM via mma: C[64][288]. 12 warps = (m-tile wid&3, n-third wid>>2) ----
    {
        const int m0 = (wid & 3) * 16;
        const int tb = (wid >> 2) * 12;    // fragment n-tile base (12 tiles per warp)
        float acc[12][4];
        #pragma unroll
        for (int nt = 0; nt < 12; ++nt)
            #pragma unroll
            for (int q = 0; q < 4; ++q) acc[nt][q] = 0.f;
        #pragma unroll
        for (int ks = 0; ks < 6; ++ks) {
            const int ra = (m0 + lg) * 104 + ks * 16 + tg * 2;
            const u32 ah0 = *(u32*)(smc + AT_XH + ra * 2);
            const u32 ah1 = *(u32*)(smc + AT_XH + (ra + 8 * 104) * 2);
            const u32 ah2 = *(u32*)(smc + AT_XH + (ra + 8) * 2);
            const u32 ah3 = *(u32*)(smc + AT_XH + (ra + 8 * 104 + 8) * 2);
            const u32 al0 = *(u32*)(smc + AT_XL + ra * 2);
            const u32 al1 = *(u32*)(smc + AT_XL + (ra + 8 * 104) * 2);
            const u32 al2 = *(u32*)(smc + AT_XL + (ra + 8) * 2);
            const u32 al3 = *(u32*)(smc + AT_XL + (ra + 8 * 104 + 8) * 2);
            #pragma unroll
            for (int nt = 0; nt < 12; ++nt) {
                const int fi = ((tb + nt) * 6 + ks) * 32 + lane;
                mma3(acc[nt], ah0, ah1, ah2, ah3, al0, al1, al2, al3,
                     g_qf_h[fi], g_qf_l[fi]);
            }
        }
        const int nb = (wid >> 2) * 96;
        #pragma unroll
        for (int nt = 0; nt < 12; ++nt) {
            const int n0 = nb + nt * 8 + tg * 2;
            const float b0v = qkv_b[n0], b1v = qkv_b[n0 + 1];
            *(float2*)&qk[(m0 + lg) * 292 + n0] =
                make_float2(acc[nt][0] + b0v, acc[nt][1] + b1v);
            *(float2*)&qk[(m0 + lg + 8) * 292 + n0] =
                make_float2(acc[nt][2] + b0v, acc[nt][3] + b1v);
        }
    }
    __syncthreads();

    // ---- S = q k^T * scale + bias + mask (scalar, all heads) ----
    for (int gg = tid; gg < 768; gg += 384) {
        const int h = gg >> 7;
        const int rem = gg & 127;
        const int n0 = rem & 15;
        const int m0 = (rem >> 4) << 3;
        const int qo = h * 16, ko = 96 + h * 16;
        float qv[4][16];
        #pragma unroll
        for (int i = 0; i < 4; ++i) {
            #pragma unroll
            for (int k = 0; k < 4; ++k) {
                const float4 v = ld4s(&qk[(n0 + 16 * i) * 292 + qo + 4 * k]);
                qv[i][4 * k] = v.x; qv[i][4 * k + 1] = v.y;
                qv[i][4 * k + 2] = v.z; qv[i][4 * k + 3] = v.w;
            }
        }
        float acc[4][8];
        #pragma unroll
        for (int i = 0; i < 4; ++i)
            #pragma unroll
            for (int j = 0; j < 8; ++j) acc[i][j] = 0.f;
        #pragma unroll
        for (int j = 0; j < 8; ++j) {
            float kv[16];
            #pragma unroll
            for (int k = 0; k < 4; ++k) {
                const float4 v = ld4s(&qk[(m0 + j) * 292 + ko + 4 * k]);
                kv[4 * k] = v.x; kv[4 * k + 1] = v.y;
                kv[4 * k + 2] = v.z; kv[4 * k + 3] = v.w;
            }
            #pragma unroll
            for (int i = 0; i < 4; ++i) {
                float a = 0.f;
                #pragma unroll
                for (int d = 0; d < 16; ++d) a += qv[i][d] * kv[d];
                acc[i][j] = a;
            }
        }
        #pragma unroll
        for (int i = 0; i < 4; ++i) {
            const int n = n0 + 16 * i;
            const int r1 = n >> 3, c1 = n & 7;
            const int rgn = rg[n];
            float vo[8];
            #pragma unroll
            for (int j = 0; j < 8; ++j) {
                const int m = m0 + j;
                const int r2 = m >> 3, c2 = m & 7;
                float s = acc[i][j] * 0.25f
                        + rpb[((r1 - r2 + 7) * 15 + (c1 - c2 + 7)) * HEADS + h];
                if (rgn != rg[m]) s -= 100.0f;
                vo[j] = s;
            }
            *reinterpret_cast<float4*>(&sa[(h * 64 + n) * 68 + m0]) =
                make_float4(vo[0], vo[1], vo[2], vo[3]);
            *reinterpret_cast<float4*>(&sa[(h * 64 + n) * 68 + m0 + 4]) =
                make_float4(vo[4], vo[5], vo[6], vo[7]);
        }
    }
    __syncthreads();

    // ---- softmax: 384 rows, one per thread ----
    {
        float* row = sa + tid * 68;
        float mx = -1e30f;
        #pragma unroll
        for (int m = 0; m < 64; m += 4) {
            float4 v = *reinterpret_cast<float4*>(&row[m]);
            mx = fmaxf(mx, fmaxf(fmaxf(v.x, v.y), fmaxf(v.z, v.w)));
        }
        float sum = 0.f;
        #pragma unroll
        for (int m = 0; m < 64; m += 4) {
            float4 v = *reinterpret_cast<float4*>(&row[m]);
            v.x = __expf(v.x - mx); v.y = __expf(v.y - mx);
            v.z = __expf(v.z - mx); v.w = __expf(v.w - mx);
            sum += v.x + v.y + v.z + v.w;
            *reinterpret_cast<float4*>(&row[m]) = v;
        }
        const float inv = 1.0f / sum;
        #pragma unroll
        for (int m = 0; m < 64; m += 4) {
            float4 v = *reinterpret_cast<float4*>(&row[m]);
            v.x *= inv; v.y *= inv; v.z *= inv; v.w *= inv;
            *reinterpret_cast<float4*>(&row[m]) = v;
        }
    }
    __syncthreads();

    // ---- PV (scalar) -> write output pre-split bf16 hi/lo into X region ----
    if (tid < 192) {
        const int h = tid / 32;
        const int rem = tid & 31;
        const int n0 = rem & 15;
        const int d0 = (rem >> 4) << 3;
        const int vofs = 192 + h * 16 + d0;
        float acc[4][8];
        #pragma unroll
        for (int i = 0; i < 4; ++i)
            #pragma unroll
            for (int j = 0; j < 8; ++j) acc[i][j] = 0.f;
        for (int m0 = 0; m0 < 64; m0 += 4) {
            float p4[4][4];
            #pragma unroll
            for (int i = 0; i < 4; ++i) {
                const float4 u = ld4s(&sa[(h * 64 + n0 + 16 * i) * 68 + m0]);
                p4[i][0] = u.x; p4[i][1] = u.y; p4[i][2] = u.z; p4[i][3] = u.w;
            }
            #pragma unroll
            for (int mi = 0; mi < 4; ++mi) {
                const float4 v0 = ld4s(&qk[(m0 + mi) * 292 + vofs]);
                const float4 v1 = ld4s(&qk[(m0 + mi) * 292 + vofs + 4]);
                #pragma unroll
                for (int i = 0; i < 4; ++i) {
                    const float p = p4[i][mi];
                    acc[i][0] += p * v0.x; acc[i][1] += p * v0.y;
                    acc[i][2] += p * v0.z; acc[i][3] += p * v0.w;
                    acc[i][4] += p * v1.x; acc[i][5] += p * v1.y;
                    acc[i][6] += p * v1.z; acc[i][7] += p * v1.w;
                }
            }
        }
        #pragma unroll
        for (int i = 0; i < 4; ++i) {
            const int base = (n0 + 16 * i) * 104 + h * 16 + d0;
            #pragma unroll
            for (int j = 0; j < 4; ++j) {
                unsigned short h0, l0, h1, l1;
                bf16_split(acc[i][2 * j], h0, l0);
                bf16_split(acc[i][2 * j + 1], h1, l1);
                *(u32*)(smc + AT_XH + (base + 2 * j) * 2) = pack2(h0, h1);
                *(u32*)(smc + AT_XL + (base + 2 * j) * 2) = pack2(l0, l1);
            }
        }
    }
    __syncthreads();

    // ---- proj GEMM via mma: C[64][96]. 12 warps = (m-tile wid&3, n-third wid>>2) ----
    {
        const int m0 = (wid & 3) * 16;
        const int tb = (wid >> 2) * 4;     // 4 fragment n-tiles per warp
        float acc[4][4];
        #pragma unroll
        for (int nt = 0; nt < 4; ++nt)
            #pragma unroll
            for (int q = 0; q < 4; ++q) acc[nt][q] = 0.f;
        #pragma unroll
        for (int ks = 0; ks < 6; ++ks) {
            const int ra = (m0 + lg) * 104 + ks * 16 + tg * 2;
            const u32 ah0 = *(u32*)(smc + AT_XH + ra * 2);
            const u32 ah1 = *(u32*)(smc + AT_XH + (ra + 8 * 104) * 2);
            const u32 ah2 = *(u32*)(smc + AT_XH + (ra + 8) * 2);
            const u32 ah3 = *(u32*)(smc + AT_XH + (ra + 8 * 104 + 8) * 2);
            const u32 al0 = *(u32*)(smc + AT_XL + ra * 2);
            const u32 al1 = *(u32*)(smc + AT_XL + (ra + 8 * 104) * 2);
            const u32 al2 = *(u32*)(smc + AT_XL + (ra + 8) * 2);
            const u32 al3 = *(u32*)(smc + AT_XL + (ra + 8 * 104 + 8) * 2);
            #pragma unroll
            for (int nt = 0; nt < 4; ++nt) {
                const int fi = ((tb + nt) * 6 + ks) * 32 + lane;
                mma3(acc[nt], ah0, ah1, ah2, ah3, al0, al1, al2, al3,
                     g_pf_h[fi], g_pf_l[fi]);
            }
        }
        const int nb = (wid >> 2) * 32;
        #pragma unroll
        for (int nt = 0; nt < 4; ++nt) {
            const int n0 = nb + nt * 8 + tg * 2;
            const float b0v = proj_b[n0], b1v = proj_b[n0 + 1];
            *(float2*)&g_y[(win * 64 + m0 + lg) * 96 + n0] =
                make_float2(acc[nt][0] + b0v, acc[nt][1] + b1v);
            *(float2*)&g_y[(win * 64 + m0 + lg + 8) * 96 + n0] =
                make_float2(acc[nt][2] + b0v, acc[nt][3] + b1v);
        }
    }
}

// ============================================================================
// Kernel D: window reverse + un-shift + residual + LayerNorm2 -> transposed out.
// 256 threads, 256 pixels per block, grid (2, 512). smem 96x260 fp32.
// ============================================================================
__global__ __launch_bounds__(256, 2)
void k_res_ln2(const float* __restrict__ x,
               const float* __restrict__ n2w,
               const float* __restrict__ n2b) {
    extern __shared__ float s[];
    const int h = blockIdx.y;
    const int w0 = blockIdx.x * 256;
    const int t = threadIdx.x;

    for (int i = t; i < 96 * 64; i += 256) {
        const int c = i >> 6, q = i & 63;
        *reinterpret_cast<float4*>(&s[c * 260 + 4 * q]) =
            ld4s(&x[c * HWSZ + h * WW + w0 + 4 * q]);
    }
    __syncthreads();

    const int hs = (h - SHIFT) & (HH - 1);
    const int winr = (hs >> 3) * 64;
    const int tokr = (hs & 7) << 3;
    for (int i = t; i < 256 * 96; i += 256) {
        const int tt = i / 96, c = i - tt * 96;
        const int ws = (w0 + tt - SHIFT) & (WW - 1);
        s[c * 260 + tt] += g_y[((winr + (ws >> 3)) * NTOK + tokr + (ws & 7)) * CC + c];
    }
    __syncthreads();

    float mu = 0.f;
    #pragma unroll 8
    for (int c = 0; c < CC; ++c) mu += s[c * 260 + t];
    mu *= (1.0f / CC);
    float var = 0.f;
    #pragma unroll 8
    for (int c = 0; c < CC; ++c) { float d = s[c * 260 + t] - mu; var += d * d; }
    var *= (1.0f / CC);
    const float rstd = rsqrtf(var + EPS);

    const int p = h * WW + w0 + t;
    #pragma unroll 4
    for (int c = 0; c < CC; ++c) {
        const float v = s[c * 260 + t];
        g_x1T[c * HWSZ + p] = v;
        g_hnT[c * HWSZ + p] = (v - mu) * rstd * n2w[c] + n2b[c];
    }
}

// ============================================================================
// Kernel E: MLP via mma.sync bf16 split; fragment-major B from global (LDG.64).
// 2048 CTAs x 256 threads (8 warps), 128 pixels per CTA.  (unchanged from R15)
// smem: A1 hi @0 / lo @26624 (128x104 bf16); A2 hi @53248 / lo @88064 (128x136)
// ============================================================================
#define OFF_A1H 0
#define OFF_A1L 26624
#define OFF_A2H 53248
#define OFF_A2L 88064
#define SMEM_MLP 122880

__global__ __launch_bounds__(256, 1)
void k_mlp_mma(const float* __restrict__ fc1_b,
               const float* __restrict__ fc2_b,
               float* __restrict__ out) {
    extern __shared__ char smc[];
    const int tid = threadIdx.x;
    const int wid = tid >> 5;
    const int lane = tid & 31;
    const int lg = lane >> 2;      // 0..7
    const int tg = lane & 3;       // 0..3
    const int p0 = blockIdx.x * 128;
    const int m0 = wid * 16;       // warp's M rows

    for (int i = tid; i < 128 * 48; i += 256) {
        const int p = i & 127;
        const int c0 = (i >> 7) << 1;
        const float v0 = g_hnT[c0 * HWSZ + p0 + p];
        const float v1 = g_hnT[(c0 + 1) * HWSZ + p0 + p];
        unsigned short h0, l0, h1, l1;
        bf16_split(v0, h0, l0);
        bf16_split(v1, h1, l1);
        *(u32*)(smc + OFF_A1H + (p * 104 + c0) * 2) = pack2(h0, h1);
        *(u32*)(smc + OFF_A1L + (p * 104 + c0) * 2) = pack2(l0, l1);
    }
    __syncthreads();

    float acc2[12][4];
    #pragma unroll
    for (int nt = 0; nt < 12; ++nt)
        #pragma unroll
        for (int q = 0; q < 4; ++q) acc2[nt][q] = 0.f;

    for (int nc = 0; nc < 3; ++nc) {
        float acc1[16][4];
        #pragma unroll
        for (int nt = 0; nt < 16; ++nt)
            #pragma unroll
            for (int q = 0; q < 4; ++q) acc1[nt][q] = 0.f;

        #pragma unroll
        for (int ks = 0; ks < 6; ++ks) {
            const int ra = (m0 + lg) * 104 + ks * 16 + tg * 2;
            const u32 ah0 = *(u32*)(smc + OFF_A1H + ra * 2);
            const u32 ah1 = *(u32*)(smc + OFF_A1H + (ra + 8 * 104) * 2);
            const u32 ah2 = *(u32*)(smc + OFF_A1H + (ra + 8) * 2);
            const u32 ah3 = *(u32*)(smc + OFF_A1H + (ra + 8 * 104 + 8) * 2);
            const u32 al0 = *(u32*)(smc + OFF_A1L + ra * 2);
            const u32 al1 = *(u32*)(smc + OFF_A1L + (ra + 8 * 104) * 2);
            const u32 al2 = *(u32*)(smc + OFF_A1L + (ra + 8) * 2);
            const u32 al3 = *(u32*)(smc + OFF_A1L + (ra + 8 * 104 + 8) * 2);
            #pragma unroll
            for (int nt = 0; nt < 16; ++nt) {
                const int fi = ((nc * 16 + nt) * 6 + ks) * 32 + lane;
                mma3(acc1[nt], ah0, ah1, ah2, ah3, al0, al1, al2, al3,
                     g_w1f_h[fi], g_w1f_l[fi]);
            }
        }

        #pragma unroll
        for (int nt = 0; nt < 16; ++nt) {
            const int jb = nc * 128 + nt * 8 + tg * 2;
            const float bv0 = fc1_b[jb], bv1 = fc1_b[jb + 1];
            float x0 = acc1[nt][0] + bv0;
            float x1 = acc1[nt][1] + bv1;
            float y0 = acc1[nt][2] + bv0;
            float y1 = acc1[nt][3] + bv1;
            x0 = 0.5f * x0 * (1.0f + erff(x0 * 0.70710678118654752f));
            x1 = 0.5f * x1 * (1.0f + erff(x1 * 0.70710678118654752f));
            y0 = 0.5f * y0 * (1.0f + erff(y0 * 0.70710678118654752f));
            y1 = 0.5f * y1 * (1.0f + erff(y1 * 0.70710678118654752f));
            unsigned short h0, l0, h1, l1;
            const int col = nt * 8 + tg * 2;
            bf16_split(x0, h0, l0); bf16_split(x1, h1, l1);
            *(u32*)(smc + OFF_A2H + ((m0 + lg) * 136 + col) * 2) = pack2(h0, h1);
            *(u32*)(smc + OFF_A2L + ((m0 + lg) * 136 + col) * 2) = pack2(l0, l1);
            bf16_split(y0, h0, l0); bf16_split(y1, h1, l1);
            *(u32*)(smc + OFF_A2H + ((m0 + lg + 8) * 136 + col) * 2) = pack2(h0, h1);
            *(u32*)(smc + OFF_A2L + ((m0 + lg + 8) * 136 + col) * 2) = pack2(l0, l1);
        }
        __syncthreads();

        #pragma unroll
        for (int ks = 0; ks < 8; ++ks) {
            const int ra = (m0 + lg) * 136 + ks * 16 + tg * 2;
            const u32 ah0 = *(u32*)(smc + OFF_A2H + ra * 2);
            const u32 ah1 = *(u32*)(smc + OFF_A2H + (ra + 8 * 136) * 2);
            const u32 ah2 = *(u32*)(smc + OFF_A2H + (ra + 8) * 2);
            const u32 ah3 = *(u32*)(smc + OFF_A2H + (ra + 8 * 136 + 8) * 2);
            const u32 al0 = *(u32*)(smc + OFF_A2L + ra * 2);
            const u32 al1 = *(u32*)(smc + OFF_A2L + (ra + 8 * 136) * 2);
            const u32 al2 = *(u32*)(smc + OFF_A2L + (ra + 8) * 2);
            const u32 al3 = *(u32*)(smc + OFF_A2L + (ra + 8 * 136 + 8) * 2);
            #pragma unroll
            for (int nt = 0; nt < 12; ++nt) {
                const int fi = (nt * 24 + nc * 8 + ks) * 32 + lane;
                mma3(acc2[nt], ah0, ah1, ah2, ah3, al0, al1, al2, al3,
                     g_w2f_h[fi], g_w2f_l[fi]);
            }
        }
        __syncthreads();
    }

    const int pA = p0 + m0 + lg;
    const int pB = pA + 8;
    #pragma unroll
    for (int nt = 0; nt < 12; ++nt) {
        const int r0c = nt * 8 + tg * 2;
        const float b0v = fc2_b[r0c], b1v = fc2_b[r0c + 1];
        out[r0c * HWSZ + pA]       = acc2[nt][0] + b0v + g_x1T[r0c * HWSZ + pA];
        out[(r0c + 1) * HWSZ + pA] = acc2[nt][1] + b1v + g_x1T[(r0c + 1) * HWSZ + pA];
        out[r0c * HWSZ + pB]       = acc2[nt][2] + b0v + g_x1T[r0c * HWSZ + pB];
        out[(r0c + 1) * HWSZ + pB] = acc2[nt][3] + b1v + g_x1T[(r0c + 1) * HWSZ + pB];
    }
}

// ============================================================================
extern "C" void kernel_launch(void* const* d_in, const int* in_sizes, int n_in,
                              void* d_out, int out_size) {
    const float* x      = (const float*)d_in[0];
    const float* n1w    = (const float*)d_in[1];
    const float* n1b    = (const float*)d_in[2];
    const float* qkv_w  = (const float*)d_in[3];
    const float* qkv_b  = (const float*)d_in[4];
    const float* rpb    = (const float*)d_in[5];
    const float* proj_w = (const float*)d_in[6];
    const float* proj_b = (const float*)d_in[7];
    const float* n2w    = (const float*)d_in[8];
    const float* n2b    = (const float*)d_in[9];
    const float* fc1_w  = (const float*)d_in[10];
    const float* fc1_b  = (const float*)d_in[11];
    const float* fc2_w  = (const float*)d_in[12];
    const float* fc2_b  = (const float*)d_in[13];
    float* out = (float*)d_out;

    cudaFuncSetAttribute(k_ln1_window, cudaFuncAttributeMaxDynamicSharedMemorySize, SMEM_LN);
    cudaFuncSetAttribute(k_res_ln2,    cudaFuncAttributeMaxDynamicSharedMemorySize, SMEM_LN);
    cudaFuncSetAttribute(k_attn,       cudaFuncAttributeMaxDynamicSharedMemorySize, SMEM_ATTN);
    cudaFuncSetAttribute(k_mlp_mma,    cudaFuncAttributeMaxDynamicSharedMemorySize, SMEM_MLP);

    k_split_w<<<108, 256>>>(qkv_w, proj_w, fc1_w, fc2_w);
    k_ln1_window<<<dim3(2, 512), 256, SMEM_LN>>>(x, n1w, n1b);
    k_attn<<<NWIN, 384, SMEM_ATTN>>>(qkv_b, rpb, proj_b);
    k_res_ln2<<<dim3(2, 512), 256, SMEM_LN>>>(x, n2w, n2b);
    k_mlp_mma<<<HWSZ / 128, 256, SMEM_MLP>>>(fc1_b, fc2_b, out);
}

// round 17
// speedup vs baseline: 1.7127x; 1.0268x over previous
#include <cuda_runtime.h>
#include <cuda_bf16.h>
#include <math.h>

// ---------------- problem constants ----------------
#define HH 512
#define WW 512
#define CC 96
#define HWSZ (HH * WW)            // 262144
#define WIN 8
#define SHIFT 4
#define NTOK 64
#define NWIN 4096
#define HEADS 6
#define HD 16
#define MLPH 384
#define EPS 1e-5f

typedef unsigned int u32;
typedef unsigned long long u64b;

__device__ __forceinline__ float4 ld4s(const float* p) {
    return *reinterpret_cast<const float4*>(p);
}

// ---------------- scratch ----------------
__device__ float g_xw[NWIN * NTOK * CC];   // LN1'd, shifted, windowed tokens [win][tok][96]
__device__ float g_y[NWIN * NTOK * CC];    // attention+proj output [win][tok][96]
__device__ float g_x1T[CC * HWSZ];         // residual-1, TRANSPOSED [c][p]
__device__ float g_hnT[CC * HWSZ];         // LN2 output,  TRANSPOSED [c][p]

// ---------------- fragment-major pre-split weights ----------------
#define QF_N  6912    // qkv:  36 ntiles * 6 ks * 32
#define PF_N  2304    // proj: 12 * 6 * 32
#define W1F_N 9216    // fc1:  48 * 6 * 32
#define W2F_N 9216    // fc2:  12 * 24 * 32
__device__ u64b g_qf_h[QF_N],  g_qf_l[QF_N];
__device__ u64b g_pf_h[PF_N],  g_pf_l[PF_N];
__device__ u64b g_w1f_h[W1F_N], g_w1f_l[W1F_N];
__device__ u64b g_w2f_h[W2F_N], g_w2f_l[W2F_N];

// ---------------- bf16 split helpers ----------------
__device__ __forceinline__ void bf16_split(float v, unsigned short& h, unsigned short& l) {
    __nv_bfloat16 hb = __float2bfloat16(v);
    __nv_bfloat16 lb = __float2bfloat16(v - __bfloat162float(hb));
    h = __bfloat16_as_ushort(hb);
    l = __bfloat16_as_ushort(lb);
}
__device__ __forceinline__ u32 pack2(unsigned short a, unsigned short b) {
    return (u32)a | ((u32)b << 16);
}

// mma.sync m16n8k16 bf16 (baseline sm_80+; valid for plain sm_103 target)
__device__ __forceinline__ void mma_bf16(float* c, u32 a0, u32 a1, u32 a2, u32 a3,
                                         u32 b0, u32 b1) {
    asm volatile(
        "mma.sync.aligned.m16n8k16.row.col.f32.bf16.bf16.f32 "
        "{%0,%1,%2,%3}, {%4,%5,%6,%7}, {%8,%9}, {%0,%1,%2,%3};"
        : "+f"(c[0]), "+f"(c[1]), "+f"(c[2]), "+f"(c[3])
        : "r"(a0), "r"(a1), "r"(a2), "r"(a3), "r"(b0), "r"(b1));
}
__device__ __forceinline__ void mma3(float* c,
                                     u32 ah0, u32 ah1, u32 ah2, u32 ah3,
                                     u32 al0, u32 al1, u32 al2, u32 al3,
                                     u64b bh, u64b bl) {
    const u32 bh0 = (u32)bh, bh1 = (u32)(bh >> 32);
    const u32 bl0 = (u32)bl, bl1 = (u32)(bl >> 32);
    mma_bf16(c, ah0, ah1, ah2, ah3, bh0, bh1);
    mma_bf16(c, ah0, ah1, ah2, ah3, bl0, bl1);
    mma_bf16(c, al0, al1, al2, al3, bh0, bh1);
}
__device__ __forceinline__ void mma3b(float* c,
                                      u32 ah0, u32 ah1, u32 ah2, u32 ah3,
                                      u32 al0, u32 al1, u32 al2, u32 al3,
                                      u32 bh0, u32 bh1, u32 bl0, u32 bl1) {
    mma_bf16(c, ah0, ah1, ah2, ah3, bh0, bh1);
    mma_bf16(c, ah0, ah1, ah2, ah3, bl0, bl1);
    mma_bf16(c, al0, al1, al2, al3, bh0, bh1);
}

// ============================================================================
// Kernel W: one-time split of all weights into fragment-major bf16 hi/lo u64.
// ============================================================================
__device__ __forceinline__ void split_slot(const float* __restrict__ W, int K,
                                           int ntile, int ks, int lane,
                                           u64b& hv, u64b& lv) {
    const int row = ntile * 8 + (lane >> 2);
    const int base = row * K + 2 * (ks * 8 + (lane & 3));
    unsigned short h0, l0, h1, l1, h2, l2, h3, l3;
    bf16_split(W[base], h0, l0);
    bf16_split(W[base + 1], h1, l1);
    bf16_split(W[base + 8], h2, l2);
    bf16_split(W[base + 9], h3, l3);
    hv = (u64b)pack2(h0, h1) | ((u64b)pack2(h2, h3) << 32);
    lv = (u64b)pack2(l0, l1) | ((u64b)pack2(l2, l3) << 32);
}

__global__ void k_split_w(const float* __restrict__ qkv_w, const float* __restrict__ proj_w,
                          const float* __restrict__ fc1_w, const float* __restrict__ fc2_w) {
    const int i = blockIdx.x * 256 + threadIdx.x;
    u64b hv, lv;
    if (i < QF_N) {
        const int s = i;
        split_slot(qkv_w, 96, s / 192, (s / 32) % 6, s & 31, hv, lv);
        g_qf_h[s] = hv; g_qf_l[s] = lv;
    } else if (i < QF_N + PF_N) {
        const int s = i - QF_N;
        split_slot(proj_w, 96, s / 192, (s / 32) % 6, s & 31, hv, lv);
        g_pf_h[s] = hv; g_pf_l[s] = lv;
    } else if (i < QF_N + PF_N + W1F_N) {
        const int s = i - QF_N - PF_N;
        split_slot(fc1_w, 96, s / 192, (s / 32) % 6, s & 31, hv, lv);
        g_w1f_h[s] = hv; g_w1f_l[s] = lv;
    } else if (i < QF_N + PF_N + W1F_N + W2F_N) {
        const int s = i - QF_N - PF_N - W1F_N;
        split_slot(fc2_w, 384, s / 768, (s / 32) % 24, s & 31, hv, lv);
        g_w2f_h[s] = hv; g_w2f_l[s] = lv;
    }
}

// ============================================================================
// Kernel A: NCHW read + LayerNorm1 + cyclic shift + window partition.
// 256 threads, 256 pixels per block, grid (2, 512). smem 96x260 fp32.
// ============================================================================
#define SMEM_LN ((96 * 260 + 512) * 4)
__global__ __launch_bounds__(256, 2)
void k_ln1_window(const float* __restrict__ x,
                  const float* __restrict__ n1w,
                  const float* __restrict__ n1b) {
    extern __shared__ float s[];
    const int h = blockIdx.y;
    const int w0 = blockIdx.x * 256;
    const int t = threadIdx.x;

    for (int i = t; i < 96 * 64; i += 256) {
        const int c = i >> 6, q = i & 63;
        *reinterpret_cast<float4*>(&s[c * 260 + 4 * q]) =
            ld4s(&x[c * HWSZ + h * WW + w0 + 4 * q]);
    }
    __syncthreads();

    float mu = 0.f;
    #pragma unroll 8
    for (int c = 0; c < CC; ++c) mu += s[c * 260 + t];
    mu *= (1.0f / CC);
    float var = 0.f;
    #pragma unroll 8
    for (int c = 0; c < CC; ++c) { float d = s[c * 260 + t] - mu; var += d * d; }
    var *= (1.0f / CC);
    const float rstd = rsqrtf(var + EPS);
    #pragma unroll 8
    for (int c = 0; c < CC; ++c)
        s[c * 260 + t] = (s[c * 260 + t] - mu) * rstd * n1w[c] + n1b[c];
    __syncthreads();

    const int hs = (h - SHIFT) & (HH - 1);
    const int winr = (hs >> 3) * 64;
    const int tokr = (hs & 7) << 3;
    // vectorized scatter: 4 channels per STG.128
    for (int i = t; i < 256 * 24; i += 256) {
        const int tt = i / 24, c4 = (i - tt * 24) * 4;
        const int ws = (w0 + tt - SHIFT) & (WW - 1);
        const float4 v = make_float4(s[c4 * 260 + tt], s[(c4 + 1) * 260 + tt],
                                     s[(c4 + 2) * 260 + tt], s[(c4 + 3) * 260 + tt]);
        *reinterpret_cast<float4*>(
            &g_xw[((winr + (ws >> 3)) * NTOK + tokr + (ws & 7)) * CC + c4]) = v;
    }
}

// ============================================================================
// Kernel C: per-window attention. qkv + S + proj on tensor cores.
// 384 threads (12 warps).
// smem (bytes):
//   [0,13312)        X / PV-out hi (64x104 bf16)
//   [13312,26624)    X / PV-out lo
//   [26624,52224)    qk hi  (64 x 200 bf16: q cols 0..95, k cols 96..191)
//   [52224,77824)    qk lo
//   [77824,103424)   v fp32 (64 x 100)
//   [103424,207872)  sa fp32 [6][64][68]
// ============================================================================
#define AT_XH 0
#define AT_XL 13312
#define AT_QH 26624
#define AT_QL 52224
#define AT_V  77824
#define AT_SA 103424
#define SMEM_ATTN 207872

__global__ __launch_bounds__(384, 1)
void k_attn(const float* __restrict__ qkv_b,
            const float* __restrict__ rpb,
            const float* __restrict__ proj_b) {
    extern __shared__ char smc[];
    float* vbuf = (float*)(smc + AT_V);    // [64][100]
    float* sa   = (float*)(smc + AT_SA);   // [6][64][68]
    __shared__ int rg[64];

    const int win = blockIdx.x;
    const int tid = threadIdx.x;
    const int wid = tid >> 5;
    const int lane = tid & 31;
    const int lg = lane >> 2;      // 0..7
    const int tg = lane & 3;       // 0..3
    const int wi = win >> 6, wj = win & 63;

    // ---- stage X: split LN1'd window tokens to bf16 hi/lo ----
    const float* src = g_xw + win * (NTOK * CC);
    for (int i = tid; i < 64 * 48; i += 384) {
        const int tok = i / 48, k2 = i - tok * 48;
        unsigned short h0, l0, h1, l1;
        bf16_split(src[tok * 96 + 2 * k2], h0, l0);
        bf16_split(src[tok * 96 + 2 * k2 + 1], h1, l1);
        const int off = (tok * 104 + 2 * k2) * 2;
        *(u32*)(smc + AT_XH + off) = pack2(h0, h1);
        *(u32*)(smc + AT_XL + off) = pack2(l0, l1);
    }
    if (tid < 64) {
        const int r1 = tid >> 3, c1 = tid & 7;
        const int a = (wi == 63) ? (r1 < SHIFT ? 1 : 2) : 0;
        const int b = (wj == 63) ? (c1 < SHIFT ? 1 : 2) : 0;
        rg[tid] = a * 3 + b;
    }
    __syncthreads();

    // ---- qkv GEMM via mma: C[64][288]. warp = (m-tile wid&3, third wid>>2) ----
    {
        const int m0 = (wid & 3) * 16;
        const int g2 = wid >> 2;           // 0=q, 1=k, 2=v
        const int tb = g2 * 12;
        float acc[12][4];
        #pragma unroll
        for (int nt = 0; nt < 12; ++nt)
            #pragma unroll
            for (int q = 0; q < 4; ++q) acc[nt][q] = 0.f;
        #pragma unroll
        for (int ks = 0; ks < 6; ++ks) {
            const int ra = (m0 + lg) * 104 + ks * 16 + tg * 2;
            const u32 ah0 = *(u32*)(smc + AT_XH + ra * 2);
            const u32 ah1 = *(u32*)(smc + AT_XH + (ra + 8 * 104) * 2);
            const u32 ah2 = *(u32*)(smc + AT_XH + (ra + 8) * 2);
            const u32 ah3 = *(u32*)(smc + AT_XH + (ra + 8 * 104 + 8) * 2);
            const u32 al0 = *(u32*)(smc + AT_XL + ra * 2);
            const u32 al1 = *(u32*)(smc + AT_XL + (ra + 8 * 104) * 2);
            const u32 al2 = *(u32*)(smc + AT_XL + (ra + 8) * 2);
            const u32 al3 = *(u32*)(smc + AT_XL + (ra + 8 * 104 + 8) * 2);
            #pragma unroll
            for (int nt = 0; nt < 12; ++nt) {
                const int fi = ((tb + nt) * 6 + ks) * 32 + lane;
                mma3(acc[nt], ah0, ah1, ah2, ah3, al0, al1, al2, al3,
                     g_qf_h[fi], g_qf_l[fi]);
            }
        }
        #pragma unroll
        for (int nt = 0; nt < 12; ++nt) {
            const int n0 = g2 * 96 + nt * 8 + tg * 2;
            const float b0v = qkv_b[n0], b1v = qkv_b[n0 + 1];
            const float c0 = acc[nt][0] + b0v, c1 = acc[nt][1] + b1v;
            const float c2 = acc[nt][2] + b0v, c3 = acc[nt][3] + b1v;
            if (g2 < 2) {
                // q,k: store pre-split bf16 hi/lo at [tok][n0] (stride 200)
                unsigned short h0, l0, h1, l1;
                bf16_split(c0, h0, l0); bf16_split(c1, h1, l1);
                *(u32*)(smc + AT_QH + ((m0 + lg) * 200 + n0) * 2) = pack2(h0, h1);
                *(u32*)(smc + AT_QL + ((m0 + lg) * 200 + n0) * 2) = pack2(l0, l1);
                bf16_split(c2, h0, l0); bf16_split(c3, h1, l1);
                *(u32*)(smc + AT_QH + ((m0 + lg + 8) * 200 + n0) * 2) = pack2(h0, h1);
                *(u32*)(smc + AT_QL + ((m0 + lg + 8) * 200 + n0) * 2) = pack2(l0, l1);
            } else {
                const int d = n0 - 192;
                *(float2*)&vbuf[(m0 + lg) * 100 + d] = make_float2(c0, c1);
                *(float2*)&vbuf[(m0 + lg + 8) * 100 + d] = make_float2(c2, c3);
            }
        }
    }
    __syncthreads();

    // ---- S = q k^T via mma, all heads. warp = (head wid>>1, col-half wid&1) ----
    {
        const int h = wid >> 1;
        const int half = wid & 1;
        const int qcol = h * 16;
        const int kcol = 96 + h * 16;
        // B fragments: 4 n-tiles of k rows (col-half)
        u32 bh0[4], bh1[4], bl0[4], bl1[4];
        #pragma unroll
        for (int nt = 0; nt < 4; ++nt) {
            const int rb = (half * 32 + nt * 8 + lg) * 200 + kcol + tg * 2;
            bh0[nt] = *(u32*)(smc + AT_QH + rb * 2);
            bh1[nt] = *(u32*)(smc + AT_QH + (rb + 8) * 2);
            bl0[nt] = *(u32*)(smc + AT_QL + rb * 2);
            bl1[nt] = *(u32*)(smc + AT_QL + (rb + 8) * 2);
        }
        float accS[4][4][4];
        #pragma unroll
        for (int mt = 0; mt < 4; ++mt)
            #pragma unroll
            for (int nt = 0; nt < 4; ++nt)
                #pragma unroll
                for (int q = 0; q < 4; ++q) accS[mt][nt][q] = 0.f;
        #pragma unroll
        for (int mt = 0; mt < 4; ++mt) {
            const int ra = (mt * 16 + lg) * 200 + qcol + tg * 2;
            const u32 ah0 = *(u32*)(smc + AT_QH + ra * 2);
            const u32 ah1 = *(u32*)(smc + AT_QH + (ra + 8 * 200) * 2);
            const u32 ah2 = *(u32*)(smc + AT_QH + (ra + 8) * 2);
            const u32 ah3 = *(u32*)(smc + AT_QH + (ra + 8 * 200 + 8) * 2);
            const u32 al0 = *(u32*)(smc + AT_QL + ra * 2);
            const u32 al1 = *(u32*)(smc + AT_QL + (ra + 8 * 200) * 2);
            const u32 al2 = *(u32*)(smc + AT_QL + (ra + 8) * 2);
            const u32 al3 = *(u32*)(smc + AT_QL + (ra + 8 * 200 + 8) * 2);
            #pragma unroll
            for (int nt = 0; nt < 4; ++nt)
                mma3b(accS[mt][nt], ah0, ah1, ah2, ah3, al0, al1, al2, al3,
                      bh0[nt], bh1[nt], bl0[nt], bl1[nt]);
        }
        // epilogue: scale + rpb bias + shift-mask -> sa fp32
        #pragma unroll
        for (int mt = 0; mt < 4; ++mt) {
            #pragma unroll
            for (int nt = 0; nt < 4; ++nt) {
                const int mcol = half * 32 + nt * 8 + tg * 2;
                const int r2a = mcol >> 3, c2a = mcol & 7;
                const int r2b = (mcol + 1) >> 3, c2b = (mcol + 1) & 7;
                const int rga = rg[mcol], rgb = rg[mcol + 1];
                #pragma unroll
                for (int rr = 0; rr < 2; ++rr) {
                    const int n = mt * 16 + lg + rr * 8;
                    const int r1 = n >> 3, c1 = n & 7;
                    const int rgn = rg[n];
                    float s0 = accS[mt][nt][rr * 2]     * 0.25f
                             + rpb[((r1 - r2a + 7) * 15 + (c1 - c2a + 7)) * HEADS + h];
                    float s1 = accS[mt][nt][rr * 2 + 1] * 0.25f
                             + rpb[((r1 - r2b + 7) * 15 + (c1 - c2b + 7)) * HEADS + h];
                    if (rgn != rga) s0 -= 100.0f;
                    if (rgn != rgb) s1 -= 100.0f;
                    *(float2*)&sa[(h * 64 + n) * 68 + mcol] = make_float2(s0, s1);
                }
            }
        }
    }
    __syncthreads();

    // ---- softmax: 384 rows, one per thread ----
    {
        float* row = sa + tid * 68;
        float mx = -1e30f;
        #pragma unroll
        for (int m = 0; m < 64; m += 4) {
            float4 v = *reinterpret_cast<float4*>(&row[m]);
            mx = fmaxf(mx, fmaxf(fmaxf(v.x, v.y), fmaxf(v.z, v.w)));
        }
        float sum = 0.f;
        #pragma unroll
        for (int m = 0; m < 64; m += 4) {
            float4 v = *reinterpret_cast<float4*>(&row[m]);
            v.x = __expf(v.x - mx); v.y = __expf(v.y - mx);
            v.z = __expf(v.z - mx); v.w = __expf(v.w - mx);
            sum += v.x + v.y + v.z + v.w;
            *reinterpret_cast<float4*>(&row[m]) = v;
        }
        const float inv = 1.0f / sum;
        #pragma unroll
        for (int m = 0; m < 64; m += 4) {
            float4 v = *reinterpret_cast<float4*>(&row[m]);
            v.x *= inv; v.y *= inv; v.z *= inv; v.w *= inv;
            *reinterpret_cast<float4*>(&row[m]) = v;
        }
    }
    __syncthreads();

    // ---- PV (scalar) -> write output pre-split bf16 hi/lo into X region ----
    if (tid < 192) {
        const int h = tid / 32;
        const int rem = tid & 31;
        const int n0 = rem & 15;
        const int d0 = (rem >> 4) << 3;
        const int vofs = h * 16 + d0;
        float acc[4][8];
        #pragma unroll
        for (int i = 0; i < 4; ++i)
            #pragma unroll
            for (int j = 0; j < 8; ++j) acc[i][j] = 0.f;
        for (int m0 = 0; m0 < 64; m0 += 4) {
            float p4[4][4];
            #pragma unroll
            for (int i = 0; i < 4; ++i) {
                const float4 u = ld4s(&sa[(h * 64 + n0 + 16 * i) * 68 + m0]);
                p4[i][0] = u.x; p4[i][1] = u.y; p4[i][2] = u.z; p4[i][3] = u.w;
            }
            #pragma unroll
            for (int mi = 0; mi < 4; ++mi) {
                const float4 v0 = ld4s(&vbuf[(m0 + mi) * 100 + vofs]);
                const float4 v1 = ld4s(&vbuf[(m0 + mi) * 100 + vofs + 4]);
                #pragma unroll
                for (int i = 0; i < 4; ++i) {
                    const float p = p4[i][mi];
                    acc[i][0] += p * v0.x; acc[i][1] += p * v0.y;
                    acc[i][2] += p * v0.z; acc[i][3] += p * v0.w;
                    acc[i][4] += p * v1.x; acc[i][5] += p * v1.y;
                    acc[i][6] += p * v1.z; acc[i][7] += p * v1.w;
                }
            }
        }
        #pragma unroll
        for (int i = 0; i < 4; ++i) {
            const int base = (n0 + 16 * i) * 104 + h * 16 + d0;
            #pragma unroll
            for (int j = 0; j < 4; ++j) {
                unsigned short h0, l0, h1, l1;
                bf16_split(acc[i][2 * j], h0, l0);
                bf16_split(acc[i][2 * j + 1], h1, l1);
                *(u32*)(smc + AT_XH + (base + 2 * j) * 2) = pack2(h0, h1);
                *(u32*)(smc + AT_XL + (base + 2 * j) * 2) = pack2(l0, l1);
            }
        }
    }
    __syncthreads();

    // ---- proj GEMM via mma: C[64][96]. 12 warps = (m-tile wid&3, n-third wid>>2) ----
    {
        const int m0 = (wid & 3) * 16;
        const int tb = (wid >> 2) * 4;
        float acc[4][4];
        #pragma unroll
        for (int nt = 0; nt < 4; ++nt)
            #pragma unroll
            for (int q = 0; q < 4; ++q) acc[nt][q] = 0.f;
        #pragma unroll
        for (int ks = 0; ks < 6; ++ks) {
            const int ra = (m0 + lg) * 104 + ks * 16 + tg * 2;
            const u32 ah0 = *(u32*)(smc + AT_XH + ra * 2);
            const u32 ah1 = *(u32*)(smc + AT_XH + (ra + 8 * 104) * 2);
            const u32 ah2 = *(u32*)(smc + AT_XH + (ra + 8) * 2);
            const u32 ah3 = *(u32*)(smc + AT_XH + (ra + 8 * 104 + 8) * 2);
            const u32 al0 = *(u32*)(smc + AT_XL + ra * 2);
            const u32 al1 = *(u32*)(smc + AT_XL + (ra + 8 * 104) * 2);
            const u32 al2 = *(u32*)(smc + AT_XL + (ra + 8) * 2);
            const u32 al3 = *(u32*)(smc + AT_XL + (ra + 8 * 104 + 8) * 2);
            #pragma unroll
            for (int nt = 0; nt < 4; ++nt) {
                const int fi = ((tb + nt) * 6 + ks) * 32 + lane;
                mma3(acc[nt], ah0, ah1, ah2, ah3, al0, al1, al2, al3,
                     g_pf_h[fi], g_pf_l[fi]);
            }
        }
        const int nb = (wid >> 2) * 32;
        #pragma unroll
        for (int nt = 0; nt < 4; ++nt) {
            const int n0 = nb + nt * 8 + tg * 2;
            const float b0v = proj_b[n0], b1v = proj_b[n0 + 1];
            *(float2*)&g_y[(win * 64 + m0 + lg) * 96 + n0] =
                make_float2(acc[nt][0] + b0v, acc[nt][1] + b1v);
            *(float2*)&g_y[(win * 64 + m0 + lg + 8) * 96 + n0] =
                make_float2(acc[nt][2] + b0v, acc[nt][3] + b1v);
        }
    }
}

// ============================================================================
// Kernel D: window reverse + un-shift + residual + LayerNorm2 -> transposed out.
// 256 threads, 256 pixels per block, grid (2, 512). Vectorized throughout.
// ============================================================================
__global__ __launch_bounds__(256, 2)
void k_res_ln2(const float* __restrict__ x,
               const float* __restrict__ n2w,
               const float* __restrict__ n2b) {
    extern __shared__ float s[];
    float* smu = s + 96 * 260;
    float* srs = smu + 256;
    const int h = blockIdx.y;
    const int w0 = blockIdx.x * 256;
    const int t = threadIdx.x;

    for (int i = t; i < 96 * 64; i += 256) {
        const int c = i >> 6, q = i & 63;
        *reinterpret_cast<float4*>(&s[c * 260 + 4 * q]) =
            ld4s(&x[c * HWSZ + h * WW + w0 + 4 * q]);
    }
    __syncthreads();

    const int hs = (h - SHIFT) & (HH - 1);
    const int winr = (hs >> 3) * 64;
    const int tokr = (hs & 7) << 3;
    for (int i = t; i < 256 * 24; i += 256) {
        const int tt = i / 24, c4 = (i - tt * 24) * 4;
        const int ws = (w0 + tt - SHIFT) & (WW - 1);
        const float4 v = ld4s(&g_y[((winr + (ws >> 3)) * NTOK + tokr + (ws & 7)) * CC + c4]);
        s[c4 * 260 + tt] += v.x;
        s[(c4 + 1) * 260 + tt] += v.y;
        s[(c4 + 2) * 260 + tt] += v.z;
        s[(c4 + 3) * 260 + tt] += v.w;
    }
    __syncthreads();

    float mu = 0.f;
    #pragma unroll 8
    for (int c = 0; c < CC; ++c) mu += s[c * 260 + t];
    mu *= (1.0f / CC);
    float var = 0.f;
    #pragma unroll 8
    for (int c = 0; c < CC; ++c) { float d = s[c * 260 + t] - mu; var += d * d; }
    var *= (1.0f / CC);
    smu[t] = mu;
    srs[t] = rsqrtf(var + EPS);
    __syncthreads();

    // vectorized writes: STG.128 for both outputs
    for (int i = t; i < 96 * 64; i += 256) {
        const int c = i >> 6, q4 = (i & 63) * 4;
        const int p = h * WW + w0 + q4;
        const float4 v = ld4s(&s[c * 260 + q4]);
        const float4 m4 = ld4s(&smu[q4]);
        const float4 r4 = ld4s(&srs[q4]);
        const float wv = n2w[c], bv = n2b[c];
        *reinterpret_cast<float4*>(&g_x1T[c * HWSZ + p]) = v;
        *reinterpret_cast<float4*>(&g_hnT[c * HWSZ + p]) =
            make_float4((v.x - m4.x) * r4.x * wv + bv,
                        (v.y - m4.y) * r4.y * wv + bv,
                        (v.z - m4.z) * r4.z * wv + bv,
                        (v.w - m4.w) * r4.w * wv + bv);
    }
}

// ============================================================================
// Kernel E: MLP via mma.sync bf16 split; fragment-major B from global (LDG.64).
// 2048 CTAs x 256 threads (8 warps), 128 pixels per CTA.  (unchanged)
// ============================================================================
#define OFF_A1H 0
#define OFF_A1L 26624
#define OFF_A2H 53248
#define OFF_A2L 88064
#define SMEM_MLP 122880

__global__ __launch_bounds__(256, 1)
void k_mlp_mma(const float* __restrict__ fc1_b,
               const float* __restrict__ fc2_b,
               float* __restrict__ out) {
    extern __shared__ char smc[];
    const int tid = threadIdx.x;
    const int wid = tid >> 5;
    const int lane = tid & 31;
    const int lg = lane >> 2;
    const int tg = lane & 3;
    const int p0 = blockIdx.x * 128;
    const int m0 = wid * 16;

    for (int i = tid; i < 128 * 48; i += 256) {
        const int p = i & 127;
        const int c0 = (i >> 7) << 1;
        const float v0 = g_hnT[c0 * HWSZ + p0 + p];
        const float v1 = g_hnT[(c0 + 1) * HWSZ + p0 + p];
        unsigned short h0, l0, h1, l1;
        bf16_split(v0, h0, l0);
        bf16_split(v1, h1, l1);
        *(u32*)(smc + OFF_A1H + (p * 104 + c0) * 2) = pack2(h0, h1);
        *(u32*)(smc + OFF_A1L + (p * 104 + c0) * 2) = pack2(l0, l1);
    }
    __syncthreads();

    float acc2[12][4];
    #pragma unroll
    for (int nt = 0; nt < 12; ++nt)
        #pragma unroll
        for (int q = 0; q < 4; ++q) acc2[nt][q] = 0.f;

    for (int nc = 0; nc < 3; ++nc) {
        float acc1[16][4];
        #pragma unroll
        for (int nt = 0; nt < 16; ++nt)
            #pragma unroll
            for (int q = 0; q < 4; ++q) acc1[nt][q] = 0.f;

        #pragma unroll
        for (int ks = 0; ks < 6; ++ks) {
            const int ra = (m0 + lg) * 104 + ks * 16 + tg * 2;
            const u32 ah0 = *(u32*)(smc + OFF_A1H + ra * 2);
            const u32 ah1 = *(u32*)(smc + OFF_A1H + (ra + 8 * 104) * 2);
            const u32 ah2 = *(u32*)(smc + OFF_A1H + (ra + 8) * 2);
            const u32 ah3 = *(u32*)(smc + OFF_A1H + (ra + 8 * 104 + 8) * 2);
            const u32 al0 = *(u32*)(smc + OFF_A1L + ra * 2);
            const u32 al1 = *(u32*)(smc + OFF_A1L + (ra + 8 * 104) * 2);
            const u32 al2 = *(u32*)(smc + OFF_A1L + (ra + 8) * 2);
            const u32 al3 = *(u32*)(smc + OFF_A1L + (ra + 8 * 104 + 8) * 2);
            #pragma unroll
            for (int nt = 0; nt < 16; ++nt) {
                const int fi = ((nc * 16 + nt) * 6 + ks) * 32 + lane;
                mma3(acc1[nt], ah0, ah1, ah2, ah3, al0, al1, al2, al3,
                     g_w1f_h[fi], g_w1f_l[fi]);
            }
        }

        #pragma unroll
        for (int nt = 0; nt < 16; ++nt) {
            const int jb = nc * 128 + nt * 8 + tg * 2;
            const float bv0 = fc1_b[jb], bv1 = fc1_b[jb + 1];
            float x0 = acc1[nt][0] + bv0;
            float x1 = acc1[nt][1] + bv1;
            float y0 = acc1[nt][2] + bv0;
            float y1 = acc1[nt][3] + bv1;
            x0 = 0.5f * x0 * (1.0f + erff(x0 * 0.70710678118654752f));
            x1 = 0.5f * x1 * (1.0f + erff(x1 * 0.70710678118654752f));
            y0 = 0.5f * y0 * (1.0f + erff(y0 * 0.70710678118654752f));
            y1 = 0.5f * y1 * (1.0f + erff(y1 * 0.70710678118654752f));
            unsigned short h0, l0, h1, l1;
            const int col = nt * 8 + tg * 2;
            bf16_split(x0, h0, l0); bf16_split(x1, h1, l1);
            *(u32*)(smc + OFF_A2H + ((m0 + lg) * 136 + col) * 2) = pack2(h0, h1);
            *(u32*)(smc + OFF_A2L + ((m0 + lg) * 136 + col) * 2) = pack2(l0, l1);
            bf16_split(y0, h0, l0); bf16_split(y1, h1, l1);
            *(u32*)(smc + OFF_A2H + ((m0 + lg + 8) * 136 + col) * 2) = pack2(h0, h1);
            *(u32*)(smc + OFF_A2L + ((m0 + lg + 8) * 136 + col) * 2) = pack2(l0, l1);
        }
        __syncthreads();

        #pragma unroll
        for (int ks = 0; ks < 8; ++ks) {
            const int ra = (m0 + lg) * 136 + ks * 16 + tg * 2;
            const u32 ah0 = *(u32*)(smc + OFF_A2H + ra * 2);
            const u32 ah1 = *(u32*)(smc + OFF_A2H + (ra + 8 * 136) * 2);
            const u32 ah2 = *(u32*)(smc + OFF_A2H + (ra + 8) * 2);
            const u32 ah3 = *(u32*)(smc + OFF_A2H + (ra + 8 * 136 + 8) * 2);
            const u32 al0 = *(u32*)(smc + OFF_A2L + ra * 2);
            const u32 al1 = *(u32*)(smc + OFF_A2L + (ra + 8 * 136) * 2);
            const u32 al2 = *(u32*)(smc + OFF_A2L + (ra + 8) * 2);
            const u32 al3 = *(u32*)(smc + OFF_A2L + (ra + 8 * 136 + 8) * 2);
            #pragma unroll
            for (int nt = 0; nt < 12; ++nt) {
                const int fi = (nt * 24 + nc * 8 + ks) * 32 + lane;
                mma3(acc2[nt], ah0, ah1, ah2, ah3, al0, al1, al2, al3,
                     g_w2f_h[fi], g_w2f_l[fi]);
            }
        }
        __syncthreads();
    }

    const int pA = p0 + m0 + lg;
    const int pB = pA + 8;
    #pragma unroll
    for (int nt = 0; nt < 12; ++nt) {
        const int r0c = nt * 8 + tg * 2;
        const float b0v = fc2_b[r0c], b1v = fc2_b[r0c + 1];
        out[r0c * HWSZ + pA]       = acc2[nt][0] + b0v + g_x1T[r0c * HWSZ + pA];
        out[(r0c + 1) * HWSZ + pA] = acc2[nt][1] + b1v + g_x1T[(r0c + 1) * HWSZ + pA];
        out[r0c * HWSZ + pB]       = acc2[nt][2] + b0v + g_x1T[r0c * HWSZ + pB];
        out[(r0c + 1) * HWSZ + pB] = acc2[nt][3] + b1v + g_x1T[(r0c + 1) * HWSZ + pB];
    }
}

// ============================================================================
extern "C" void kernel_launch(void* const* d_in, const int* in_sizes, int n_in,
                              void* d_out, int out_size) {
    const float* x      = (const float*)d_in[0];
    const float* n1w    = (const float*)d_in[1];
    const float* n1b    = (const float*)d_in[2];
    const float* qkv_w  = (const float*)d_in[3];
    const float* qkv_b  = (const float*)d_in[4];
    const float* rpb    = (const float*)d_in[5];
    const float* proj_w = (const float*)d_in[6];
    const float* proj_b = (const float*)d_in[7];
    const float* n2w    = (const float*)d_in[8];
    const float* n2b    = (const float*)d_in[9];
    const float* fc1_w  = (const float*)d_in[10];
    const float* fc1_b  = (const float*)d_in[11];
    const float* fc2_w  = (const float*)d_in[12];
    const float* fc2_b  = (const float*)d_in[13];
    float* out = (float*)d_out;

    cudaFuncSetAttribute(k_ln1_window, cudaFuncAttributeMaxDynamicSharedMemorySize, SMEM_LN);
    cudaFuncSetAttribute(k_res_ln2,    cudaFuncAttributeMaxDynamicSharedMemorySize, SMEM_LN);
    cudaFuncSetAttribute(k_attn,       cudaFuncAttributeMaxDynamicSharedMemorySize, SMEM_ATTN);
    cudaFuncSetAttribute(k_mlp_mma,    cudaFuncAttributeMaxDynamicSharedMemorySize, SMEM_MLP);

    k_split_w<<<108, 256>>>(qkv_w, proj_w, fc1_w, fc2_w);
    k_ln1_window<<<dim3(2, 512), 256, SMEM_LN>>>(x, n1w, n1b);
    k_attn<<<NWIN, 384, SMEM_ATTN>>>(qkv_b, rpb, proj_b);
    k_res_ln2<<<dim3(2, 512), 256, SMEM_LN>>>(x, n2w, n2b);
    k_mlp_mma<<<HWSZ / 128, 256, SMEM_MLP>>>(fc1_b, fc2_b, out);
}